// round 1
// baseline (speedup 1.0000x reference)
#include <cuda_runtime.h>
#include <cuda_bf16.h>
#include <cstdint>

#define NMAX 100000
#define EMAX 1600000
#define H 64
#define NF 18

// ---------------- scratch (device globals; no allocations allowed) ----------
__device__ __align__(128) float g_x[NMAX * 64];
__device__ __align__(128) float g_PR[NMAX * 96];   // [msg rowpart 64 | att rowpart 32]
__device__ __align__(128) float g_PC[NMAX * 96];   // [msg colpart 64 | att colpart 32]
__device__ __align__(128) float g_S[NMAX * 64];    // segment_sum(fw * h1)
__device__ __align__(128) float g_sumfw[NMAX];
__device__ __align__(128) float g_mx[64];

// ---------------- zero scratch ----------------
__global__ void k_zero(int n) {
    int i = blockIdx.x * blockDim.x + threadIdx.x;
    int stride = gridDim.x * blockDim.x;
    int tot = n * 64;
    for (int j = i; j < tot; j += stride) g_S[j] = 0.f;
    for (int j = i; j < n; j += stride) g_sumfw[j] = 0.f;
    if (i < 64) g_mx[i] = 0.f;
}

// ---------------- embed: x = relu(nf @ W + b), warp per node ----------------
__global__ __launch_bounds__(256) void k_embed(const float* __restrict__ nf,
                                               const float* __restrict__ W,
                                               const float* __restrict__ b, int n) {
    __shared__ float sW[NF * 64];
    __shared__ float sb[64];
    int tid = threadIdx.x;
    for (int i = tid; i < NF * 64; i += blockDim.x) sW[i] = W[i];
    if (tid < 64) sb[tid] = b[tid];
    __syncthreads();
    int warp = tid >> 5, lane = tid & 31;
    for (int node = blockIdx.x * 8 + warp; node < n; node += gridDim.x * 8) {
        float v = (lane < NF) ? nf[(long)node * NF + lane] : 0.f;
        float a0 = sb[2 * lane], a1 = sb[2 * lane + 1];
#pragma unroll
        for (int k = 0; k < NF; k++) {
            float xv = __shfl_sync(0xffffffffu, v, k);
            a0 += xv * sW[k * 64 + 2 * lane];
            a1 += xv * sW[k * 64 + 2 * lane + 1];
        }
        float2 r;
        r.x = fmaxf(a0, 0.f);
        r.y = fmaxf(a1, 0.f);
        *reinterpret_cast<float2*>(&g_x[(long)node * 64 + 2 * lane]) = r;
    }
}

// ---------------- per-layer precompute: PR/PC node-level GEMMs --------------
// PR[n] = x[n] @ msgW1[0:64]  (64) | x[n] @ attW1[0:64]  (32)
// PC[n] = x[n] @ msgW1[64:128](64) | x[n] @ attW1[64:128](32)
__global__ __launch_bounds__(256) void k_pre(const float* __restrict__ mW1,
                                             const float* __restrict__ aW1, int n) {
    __shared__ float sM[128 * 64];  // 32KB
    __shared__ float sA[128 * 32];  // 16KB
    int tid = threadIdx.x;
    for (int i = tid; i < 128 * 64; i += blockDim.x) sM[i] = mW1[i];
    for (int i = tid; i < 128 * 32; i += blockDim.x) sA[i] = aW1[i];
    __syncthreads();
    int warp = tid >> 5, lane = tid & 31;
    for (int node = blockIdx.x * 8 + warp; node < n; node += gridDim.x * 8) {
        float2 xv2 = *reinterpret_cast<const float2*>(&g_x[(long)node * 64 + 2 * lane]);
        float pr0 = 0, pr1 = 0, pc0 = 0, pc1 = 0, ar = 0, ac = 0;
#pragma unroll
        for (int k = 0; k < 64; k++) {
            float xv = __shfl_sync(0xffffffffu, (k & 1) ? xv2.y : xv2.x, k >> 1);
            float2 wm = *reinterpret_cast<const float2*>(&sM[k * 64 + 2 * lane]);
            float2 wm2 = *reinterpret_cast<const float2*>(&sM[(64 + k) * 64 + 2 * lane]);
            pr0 += xv * wm.x;
            pr1 += xv * wm.y;
            pc0 += xv * wm2.x;
            pc1 += xv * wm2.y;
            ar += xv * sA[k * 32 + lane];
            ac += xv * sA[(64 + k) * 32 + lane];
        }
        float2 o;
        o.x = pr0; o.y = pr1;
        *reinterpret_cast<float2*>(&g_PR[(long)node * 96 + 2 * lane]) = o;
        g_PR[(long)node * 96 + 64 + lane] = ar;
        o.x = pc0; o.y = pc1;
        *reinterpret_cast<float2*>(&g_PC[(long)node * 96 + 2 * lane]) = o;
        g_PC[(long)node * 96 + 64 + lane] = ac;
    }
}

// ---------------- edge kernel: gather PR/PC, tiny MLP tail, scatter ---------
__global__ __launch_bounds__(256) void k_edge(const int* __restrict__ row,
                                              const int* __restrict__ col,
                                              const float* __restrict__ ew,
                                              const float* __restrict__ mb1,
                                              const float* __restrict__ ab1,
                                              const float* __restrict__ aW2,
                                              const float* __restrict__ ab2, int ne) {
    __shared__ __align__(16) float sh[8][64];
    __shared__ float s_mb1[64], s_ab1[32], s_aw2[32];
    __shared__ float s_ab2;
    int tid = threadIdx.x;
    if (tid < 64) s_mb1[tid] = mb1[tid];
    else if (tid < 96) s_ab1[tid - 64] = ab1[tid - 64];
    else if (tid < 128) s_aw2[tid - 96] = aW2[tid - 96];
    else if (tid == 128) s_ab2 = ab2[0];
    __syncthreads();
    int warp = tid >> 5, lane = tid & 31;
    for (long e = (long)blockIdx.x * 8 + warp; e < ne; e += (long)gridDim.x * 8) {
        int r = row[e], c = col[e];
        float w = ew[e];
        const float* pr = &g_PR[(long)r * 96];
        const float* pc = &g_PC[(long)c * 96];
        float h1a = fmaxf(pr[lane] + pc[lane] + s_mb1[lane], 0.f);
        float h1b = fmaxf(pr[32 + lane] + pc[32 + lane] + s_mb1[32 + lane], 0.f);
        float a1 = fmaxf(pr[64 + lane] + pc[64 + lane] + s_ab1[lane], 0.f);
        float t = a1 * s_aw2[lane];
#pragma unroll
        for (int o = 16; o > 0; o >>= 1) t += __shfl_xor_sync(0xffffffffu, t, o);
        float att = 1.f / (1.f + __expf(-(t + s_ab2)));
        float fw = w * att;
        sh[warp][lane] = fw * h1a;
        sh[warp][32 + lane] = fw * h1b;
        __syncwarp();
        if (lane < 16) {
            float4 v = *reinterpret_cast<float4*>(&sh[warp][4 * lane]);
            float* dst = &g_S[(long)c * 64 + 4 * lane];
            asm volatile("red.global.add.v4.f32 [%0], {%1,%2,%3,%4};" ::"l"(dst),
                         "f"(v.x), "f"(v.y), "f"(v.z), "f"(v.w)
                         : "memory");
        } else if (lane == 16) {
            atomicAdd(&g_sumfw[c], fw);
        }
        __syncwarp();
    }
}

// ---------------- fused: agg = (S@W2 + sumfw*b2)/norm, update MLP, residual,
//                  relu, optional per-feature max  (warp per node) -----------
__global__ __launch_bounds__(256) void k_update(const float* __restrict__ W2,
                                                const float* __restrict__ b2,
                                                const float* __restrict__ U1,
                                                const float* __restrict__ ub1,
                                                const float* __restrict__ U2,
                                                const float* __restrict__ ub2, int n,
                                                int do_max) {
    extern __shared__ float sm[];
    float* sW2 = sm;                 // 64*64
    float* sU1 = sm + 4096;          // 128*64
    float* sU2 = sm + 4096 + 8192;   // 64*64
    int tid = threadIdx.x;
    for (int i = tid; i < 4096; i += blockDim.x) sW2[i] = W2[i];
    for (int i = tid; i < 8192; i += blockDim.x) sU1[i] = U1[i];
    for (int i = tid; i < 4096; i += blockDim.x) sU2[i] = U2[i];
    __syncthreads();
    int warp = tid >> 5, lane = tid & 31;
    float bb2a = b2[2 * lane], bb2b = b2[2 * lane + 1];
    float b1a = ub1[2 * lane], b1b = ub1[2 * lane + 1];
    float b2a = ub2[2 * lane], b2b = ub2[2 * lane + 1];
    float m0 = 0.f, m1 = 0.f;
    for (int node = blockIdx.x * 8 + warp; node < n; node += gridDim.x * 8) {
        float2 xv = *reinterpret_cast<const float2*>(&g_x[(long)node * 64 + 2 * lane]);
        float2 sv = *reinterpret_cast<const float2*>(&g_S[(long)node * 64 + 2 * lane]);
        float sf = g_sumfw[node];
        float inv = 1.f / fmaxf(sf, 1e-6f);
        float a0 = sf * bb2a, a1 = sf * bb2b;
#pragma unroll
        for (int k = 0; k < 64; k++) {
            float v = __shfl_sync(0xffffffffu, (k & 1) ? sv.y : sv.x, k >> 1);
            float2 wv = *reinterpret_cast<const float2*>(&sW2[k * 64 + 2 * lane]);
            a0 += v * wv.x;
            a1 += v * wv.y;
        }
        a0 *= inv;
        a1 *= inv;
        float h0 = b1a, h1 = b1b;
#pragma unroll
        for (int k = 0; k < 64; k++) {
            float v = __shfl_sync(0xffffffffu, (k & 1) ? xv.y : xv.x, k >> 1);
            float2 wv = *reinterpret_cast<const float2*>(&sU1[k * 64 + 2 * lane]);
            h0 += v * wv.x;
            h1 += v * wv.y;
        }
#pragma unroll
        for (int k = 0; k < 64; k++) {
            float v = __shfl_sync(0xffffffffu, (k & 1) ? a1 : a0, k >> 1);
            float2 wv = *reinterpret_cast<const float2*>(&sU1[(64 + k) * 64 + 2 * lane]);
            h0 += v * wv.x;
            h1 += v * wv.y;
        }
        h0 = fmaxf(h0, 0.f);
        h1 = fmaxf(h1, 0.f);
        float o0 = b2a, o1 = b2b;
#pragma unroll
        for (int k = 0; k < 64; k++) {
            float v = __shfl_sync(0xffffffffu, (k & 1) ? h1 : h0, k >> 1);
            float2 wv = *reinterpret_cast<const float2*>(&sU2[k * 64 + 2 * lane]);
            o0 += v * wv.x;
            o1 += v * wv.y;
        }
        o0 = fmaxf(o0 + xv.x, 0.f);
        o1 = fmaxf(o1 + xv.y, 0.f);
        float2 ox;
        ox.x = o0;
        ox.y = o1;
        *reinterpret_cast<float2*>(&g_x[(long)node * 64 + 2 * lane]) = ox;
        m0 = fmaxf(m0, o0);
        m1 = fmaxf(m1, o1);
    }
    if (do_max) {  // x >= 0 (post-relu), so uint compare == float compare
        atomicMax(reinterpret_cast<unsigned*>(&g_mx[2 * lane]), __float_as_uint(m0));
        atomicMax(reinterpret_cast<unsigned*>(&g_mx[2 * lane + 1]), __float_as_uint(m1));
    }
}

// ---------------- head: out = max_x @ head_W + head_b -----------------------
__global__ void k_head(const float* __restrict__ hW, const float* __restrict__ hb,
                       float* __restrict__ out) {
    int t = threadIdx.x;
    float v = g_mx[t] * hW[t];
#pragma unroll
    for (int o = 16; o > 0; o >>= 1) v += __shfl_xor_sync(0xffffffffu, v, o);
    __shared__ float s[2];
    if ((t & 31) == 0) s[t >> 5] = v;
    __syncthreads();
    if (t == 0) out[0] = s[0] + s[1] + hb[0];
}

// ---------------- launch ----------------------------------------------------
extern "C" void kernel_launch(void* const* d_in, const int* in_sizes, int n_in,
                              void* d_out, int out_size) {
    const float* nf = (const float*)d_in[0];
    const int* ei = (const int*)d_in[1];
    const float* ew = (const float*)d_in[2];
    const float* embW = (const float*)d_in[3];
    const float* embB = (const float*)d_in[4];
    const float* msgW1 = (const float*)d_in[5];
    const float* msgB1 = (const float*)d_in[6];
    const float* msgW2 = (const float*)d_in[7];
    const float* msgB2 = (const float*)d_in[8];
    const float* attW1 = (const float*)d_in[9];
    const float* attB1 = (const float*)d_in[10];
    const float* attW2 = (const float*)d_in[11];
    const float* attB2 = (const float*)d_in[12];
    const float* updW1 = (const float*)d_in[13];
    const float* updB1 = (const float*)d_in[14];
    const float* updW2 = (const float*)d_in[15];
    const float* updB2 = (const float*)d_in[16];
    const float* headW = (const float*)d_in[17];
    const float* headB = (const float*)d_in[18];
    float* out = (float*)d_out;

    int n = in_sizes[0] / NF;
    int ne = in_sizes[2];
    const int* row = ei;
    const int* col = ei + ne;

    cudaFuncSetAttribute(k_update, cudaFuncAttributeMaxDynamicSharedMemorySize, 65536);

    int nodeBlocks = (n + 7) / 8;
    int edgeBlocks = (ne + 7) / 8;

    k_embed<<<nodeBlocks, 256>>>(nf, embW, embB, n);
    for (int l = 0; l < 2; l++) {
        k_zero<<<1024, 256>>>(n);
        k_pre<<<nodeBlocks, 256>>>(msgW1 + l * 128 * 64, attW1 + l * 128 * 32, n);
        k_edge<<<edgeBlocks, 256>>>(row, col, ew, msgB1 + l * 64, attB1 + l * 32,
                                    attW2 + l * 32, attB2 + l, ne);
        k_update<<<444, 256, 65536>>>(msgW2 + l * 64 * 64, msgB2 + l * 64,
                                      updW1 + l * 128 * 64, updB1 + l * 64,
                                      updW2 + l * 64 * 64, updB2 + l * 64, n,
                                      (l == 1) ? 1 : 0);
    }
    k_head<<<1, 64>>>(headW, headB, out);
}

// round 2
// speedup vs baseline: 1.6623x; 1.6623x over previous
#include <cuda_runtime.h>
#include <cuda_bf16.h>
#include <cstdint>

#define NMAX 100000
#define EMAX 1600000
#define H 64
#define NF 18

// ---------------- scratch (device globals; no allocations allowed) ----------
__device__ __align__(128) float g_x[NMAX * 64];
__device__ __align__(128) float g_PR[NMAX * 96];   // [msg rowpart+b 64 | att rowpart+b 32]
__device__ __align__(128) float g_PC[NMAX * 96];   // [msg colpart 64 | att colpart 32]
__device__ __align__(128) float g_S[NMAX * 64];    // segment_sum(fw * h1)
__device__ __align__(128) float g_sumfw[NMAX];
__device__ __align__(128) float g_mx[64];

// ---------------- zero scratch ----------------
__global__ void k_zero(int n) {
    int i = blockIdx.x * blockDim.x + threadIdx.x;
    int stride = gridDim.x * blockDim.x;
    int tot = n * 64;
    for (int j = i; j < tot; j += stride) g_S[j] = 0.f;
    for (int j = i; j < n; j += stride) g_sumfw[j] = 0.f;
    if (i < 64) g_mx[i] = 0.f;
}

// ---------------- embed: x = relu(nf @ W + b), warp per node ----------------
__global__ __launch_bounds__(256) void k_embed(const float* __restrict__ nf,
                                               const float* __restrict__ W,
                                               const float* __restrict__ b, int n) {
    __shared__ float sW[NF * 64];
    __shared__ float sb[64];
    int tid = threadIdx.x;
    for (int i = tid; i < NF * 64; i += blockDim.x) sW[i] = W[i];
    if (tid < 64) sb[tid] = b[tid];
    __syncthreads();
    int warp = tid >> 5, lane = tid & 31;
    for (int node = blockIdx.x * 8 + warp; node < n; node += gridDim.x * 8) {
        float v = (lane < NF) ? nf[(long)node * NF + lane] : 0.f;
        float a0 = sb[2 * lane], a1 = sb[2 * lane + 1];
#pragma unroll
        for (int k = 0; k < NF; k++) {
            float xv = __shfl_sync(0xffffffffu, v, k);
            a0 += xv * sW[k * 64 + 2 * lane];
            a1 += xv * sW[k * 64 + 2 * lane + 1];
        }
        float2 r;
        r.x = fmaxf(a0, 0.f);
        r.y = fmaxf(a1, 0.f);
        *reinterpret_cast<float2*>(&g_x[(long)node * 64 + 2 * lane]) = r;
    }
}

// ---------------- per-layer precompute: PR/PC node GEMMs, 4 nodes/warp ------
// PR[n] = x[n]@msgW1[0:64] + msgb1 (64) | x[n]@attW1[0:64] + attb1 (32)
// PC[n] = x[n]@msgW1[64:128]       (64) | x[n]@attW1[64:128]       (32)
__global__ __launch_bounds__(256) void k_pre(const float* __restrict__ mW1,
                                             const float* __restrict__ aW1,
                                             const float* __restrict__ mb1,
                                             const float* __restrict__ ab1, int n) {
    extern __shared__ float dsm[];
    float* sM = dsm;             // 128*64 = 8192 floats
    float* sA = dsm + 8192;      // 128*32 = 4096 floats
    float* sx = dsm + 12288;     // 8 warps * 256 floats
    int tid = threadIdx.x;
    for (int i = tid; i < 8192; i += 256) sM[i] = mW1[i];
    for (int i = tid; i < 4096; i += 256) sA[i] = aW1[i];
    __syncthreads();
    int warp = tid >> 5, lane = tid & 31;
    float* sxw = sx + warp * 256;
    float bm0 = mb1[2 * lane], bm1 = mb1[2 * lane + 1], ba = ab1[lane];

    for (int base = (blockIdx.x * 8 + warp) * 4; base < n; base += gridDim.x * 32) {
        int nv = min(4, n - base);
        if (nv == 4) {
            const float4* src = reinterpret_cast<const float4*>(&g_x[(long)base * 64]);
            reinterpret_cast<float4*>(sxw)[lane] = src[lane];
            reinterpret_cast<float4*>(sxw)[lane + 32] = src[lane + 32];
        } else {
            for (int i = lane; i < 256; i += 32)
                sxw[i] = (i < nv * 64) ? g_x[(long)base * 64 + i] : 0.f;
        }
        __syncwarp();

        float pr0[4], pr1[4], pc0[4], pc1[4], ar[4], ac[4];
#pragma unroll
        for (int j = 0; j < 4; j++) {
            pr0[j] = bm0; pr1[j] = bm1; pc0[j] = 0.f; pc1[j] = 0.f;
            ar[j] = ba; ac[j] = 0.f;
        }
#pragma unroll 8
        for (int k = 0; k < 64; k += 2) {
            float2 wma0 = *reinterpret_cast<const float2*>(&sM[k * 64 + 2 * lane]);
            float2 wma1 = *reinterpret_cast<const float2*>(&sM[(k + 1) * 64 + 2 * lane]);
            float2 wmb0 = *reinterpret_cast<const float2*>(&sM[(64 + k) * 64 + 2 * lane]);
            float2 wmb1 = *reinterpret_cast<const float2*>(&sM[(65 + k) * 64 + 2 * lane]);
            float wa0 = sA[k * 32 + lane], wa1 = sA[(k + 1) * 32 + lane];
            float wc0 = sA[(64 + k) * 32 + lane], wc1 = sA[(65 + k) * 32 + lane];
#pragma unroll
            for (int j = 0; j < 4; j++) {
                float2 xv = *reinterpret_cast<const float2*>(&sxw[j * 64 + k]);
                pr0[j] += xv.x * wma0.x + xv.y * wma1.x;
                pr1[j] += xv.x * wma0.y + xv.y * wma1.y;
                pc0[j] += xv.x * wmb0.x + xv.y * wmb1.x;
                pc1[j] += xv.x * wmb0.y + xv.y * wmb1.y;
                ar[j] += xv.x * wa0 + xv.y * wa1;
                ac[j] += xv.x * wc0 + xv.y * wc1;
            }
        }
#pragma unroll
        for (int j = 0; j < 4; j++) {
            if (j < nv) {
                long o = (long)(base + j) * 96;
                float2 t;
                t.x = pr0[j]; t.y = pr1[j];
                *reinterpret_cast<float2*>(&g_PR[o + 2 * lane]) = t;
                g_PR[o + 64 + lane] = ar[j];
                t.x = pc0[j]; t.y = pc1[j];
                *reinterpret_cast<float2*>(&g_PC[o + 2 * lane]) = t;
                g_PC[o + 64 + lane] = ac[j];
            }
        }
        __syncwarp();
    }
}

// ---------------- edge kernel: persistent, 2 edges per warp iteration -------
__global__ __launch_bounds__(256, 3) void k_edge(const int* __restrict__ row,
                                                 const int* __restrict__ col,
                                                 const float* __restrict__ ew,
                                                 const float* __restrict__ aW2,
                                                 const float* __restrict__ ab2, int ne) {
    __shared__ __align__(16) float sh[8][128];
    __shared__ float s_aw2[32];
    int tid = threadIdx.x;
    if (tid < 32) s_aw2[tid] = aW2[tid];
    __syncthreads();
    float ab2v = __ldg(ab2);
    int warp = tid >> 5, lane = tid & 31;
    float aw2v = s_aw2[lane];
    long nw = (long)gridDim.x * 8;
    long gw = (long)blockIdx.x * 8 + warp;

    for (long e0 = gw; e0 < ne; e0 += 2 * nw) {
        long e1 = e0 + nw;
        bool has2 = (e1 < ne);
        long e1c = has2 ? e1 : e0;
        int r0 = row[e0], c0 = col[e0];
        int r1 = row[e1c], c1 = col[e1c];
        float w0 = ew[e0], w1 = ew[e1c];
        const float* pr0 = &g_PR[(long)r0 * 96];
        const float* pc0 = &g_PC[(long)c0 * 96];
        const float* pr1 = &g_PR[(long)r1 * 96];
        const float* pc1 = &g_PC[(long)c1 * 96];
        float h0a = fmaxf(pr0[lane] + pc0[lane], 0.f);
        float h0b = fmaxf(pr0[32 + lane] + pc0[32 + lane], 0.f);
        float t0 = fmaxf(pr0[64 + lane] + pc0[64 + lane], 0.f) * aw2v;
        float h1a = fmaxf(pr1[lane] + pc1[lane], 0.f);
        float h1b = fmaxf(pr1[32 + lane] + pc1[32 + lane], 0.f);
        float t1 = fmaxf(pr1[64 + lane] + pc1[64 + lane], 0.f) * aw2v;
#pragma unroll
        for (int o = 16; o > 0; o >>= 1) {
            t0 += __shfl_xor_sync(0xffffffffu, t0, o);
            t1 += __shfl_xor_sync(0xffffffffu, t1, o);
        }
        float fw0 = w0 / (1.f + __expf(-(t0 + ab2v)));
        float fw1 = w1 / (1.f + __expf(-(t1 + ab2v)));
        sh[warp][lane] = fw0 * h0a;
        sh[warp][32 + lane] = fw0 * h0b;
        sh[warp][64 + lane] = fw1 * h1a;
        sh[warp][96 + lane] = fw1 * h1b;
        __syncwarp();
        if (lane < 16) {
            float4 v = *reinterpret_cast<float4*>(&sh[warp][4 * lane]);
            float* dst = &g_S[(long)c0 * 64 + 4 * lane];
            asm volatile("red.global.add.v4.f32 [%0], {%1,%2,%3,%4};" ::"l"(dst),
                         "f"(v.x), "f"(v.y), "f"(v.z), "f"(v.w)
                         : "memory");
        } else if (has2) {
            float4 v = *reinterpret_cast<float4*>(&sh[warp][4 * lane]);
            float* dst = &g_S[(long)c1 * 64 + 4 * lane - 64];
            asm volatile("red.global.add.v4.f32 [%0], {%1,%2,%3,%4};" ::"l"(dst),
                         "f"(v.x), "f"(v.y), "f"(v.z), "f"(v.w)
                         : "memory");
        }
        if (lane == 0) atomicAdd(&g_sumfw[c0], fw0);
        if (lane == 1 && has2) atomicAdd(&g_sumfw[c1], fw1);
        __syncwarp();
    }
}

// ---------------- fused update: agg=(S@W2+sumfw*b2)/norm, upd MLP, residual,
//                  relu, optional max. 4 nodes per warp. ---------------------
__global__ __launch_bounds__(256) void k_update(const float* __restrict__ W2,
                                                const float* __restrict__ b2,
                                                const float* __restrict__ U1,
                                                const float* __restrict__ ub1,
                                                const float* __restrict__ U2,
                                                const float* __restrict__ ub2, int n,
                                                int do_max) {
    extern __shared__ float dsm[];
    float* sW2 = dsm;            // 4096
    float* sU1 = dsm + 4096;     // 8192
    float* sU2 = dsm + 12288;    // 4096
    float* sx = dsm + 16384;     // 8*256
    float* sB = dsm + 18432;     // 8*256 (S -> a -> h)
    int tid = threadIdx.x;
    for (int i = tid; i < 4096; i += 256) sW2[i] = W2[i];
    for (int i = tid; i < 8192; i += 256) sU1[i] = U1[i];
    for (int i = tid; i < 4096; i += 256) sU2[i] = U2[i];
    __syncthreads();
    int warp = tid >> 5, lane = tid & 31;
    float* sxw = sx + warp * 256;
    float* sbw = sB + warp * 256;
    float bb2a = b2[2 * lane], bb2b = b2[2 * lane + 1];
    float b1a = ub1[2 * lane], b1b = ub1[2 * lane + 1];
    float b2a = ub2[2 * lane], b2b = ub2[2 * lane + 1];
    float m0 = 0.f, m1 = 0.f;

    for (int base = (blockIdx.x * 8 + warp) * 4; base < n; base += gridDim.x * 32) {
        int nv = min(4, n - base);
        if (nv == 4) {
            const float4* srcx = reinterpret_cast<const float4*>(&g_x[(long)base * 64]);
            const float4* srcs = reinterpret_cast<const float4*>(&g_S[(long)base * 64]);
            reinterpret_cast<float4*>(sxw)[lane] = srcx[lane];
            reinterpret_cast<float4*>(sxw)[lane + 32] = srcx[lane + 32];
            reinterpret_cast<float4*>(sbw)[lane] = srcs[lane];
            reinterpret_cast<float4*>(sbw)[lane + 32] = srcs[lane + 32];
        } else {
            for (int i = lane; i < 256; i += 32) {
                sxw[i] = (i < nv * 64) ? g_x[(long)base * 64 + i] : 0.f;
                sbw[i] = (i < nv * 64) ? g_S[(long)base * 64 + i] : 0.f;
            }
        }
        __syncwarp();

        float sf[4], inv[4];
#pragma unroll
        for (int j = 0; j < 4; j++) {
            sf[j] = (j < nv) ? g_sumfw[base + j] : 1.f;
            inv[j] = 1.f / fmaxf(sf[j], 1e-6f);
        }
        // Phase 1: a = (S@W2 + sumfw*b2) / norm
        float a0[4], a1[4];
#pragma unroll
        for (int j = 0; j < 4; j++) { a0[j] = sf[j] * bb2a; a1[j] = sf[j] * bb2b; }
#pragma unroll 8
        for (int k = 0; k < 64; k += 2) {
            float2 w0 = *reinterpret_cast<const float2*>(&sW2[k * 64 + 2 * lane]);
            float2 w1 = *reinterpret_cast<const float2*>(&sW2[(k + 1) * 64 + 2 * lane]);
#pragma unroll
            for (int j = 0; j < 4; j++) {
                float2 v = *reinterpret_cast<const float2*>(&sbw[j * 64 + k]);
                a0[j] += v.x * w0.x + v.y * w1.x;
                a1[j] += v.x * w0.y + v.y * w1.y;
            }
        }
#pragma unroll
        for (int j = 0; j < 4; j++) { a0[j] *= inv[j]; a1[j] *= inv[j]; }
        __syncwarp();
#pragma unroll
        for (int j = 0; j < 4; j++) {
            float2 t; t.x = a0[j]; t.y = a1[j];
            *reinterpret_cast<float2*>(&sbw[j * 64 + 2 * lane]) = t;
        }
        __syncwarp();

        // Phase 2: h = relu(x@U1[0:64] + a@U1[64:128] + b1)
        float h0[4], h1[4];
#pragma unroll
        for (int j = 0; j < 4; j++) { h0[j] = b1a; h1[j] = b1b; }
#pragma unroll 8
        for (int k = 0; k < 64; k += 2) {
            float2 w0 = *reinterpret_cast<const float2*>(&sU1[k * 64 + 2 * lane]);
            float2 w1 = *reinterpret_cast<const float2*>(&sU1[(k + 1) * 64 + 2 * lane]);
#pragma unroll
            for (int j = 0; j < 4; j++) {
                float2 v = *reinterpret_cast<const float2*>(&sxw[j * 64 + k]);
                h0[j] += v.x * w0.x + v.y * w1.x;
                h1[j] += v.x * w0.y + v.y * w1.y;
            }
        }
#pragma unroll 8
        for (int k = 0; k < 64; k += 2) {
            float2 w0 = *reinterpret_cast<const float2*>(&sU1[(64 + k) * 64 + 2 * lane]);
            float2 w1 = *reinterpret_cast<const float2*>(&sU1[(65 + k) * 64 + 2 * lane]);
#pragma unroll
            for (int j = 0; j < 4; j++) {
                float2 v = *reinterpret_cast<const float2*>(&sbw[j * 64 + k]);
                h0[j] += v.x * w0.x + v.y * w1.x;
                h1[j] += v.x * w0.y + v.y * w1.y;
            }
        }
#pragma unroll
        for (int j = 0; j < 4; j++) {
            h0[j] = fmaxf(h0[j], 0.f);
            h1[j] = fmaxf(h1[j], 0.f);
        }
        __syncwarp();
#pragma unroll
        for (int j = 0; j < 4; j++) {
            float2 t; t.x = h0[j]; t.y = h1[j];
            *reinterpret_cast<float2*>(&sbw[j * 64 + 2 * lane]) = t;
        }
        __syncwarp();

        // Phase 3: o = relu(h@U2 + b2 + x)
        float o0[4], o1[4];
#pragma unroll
        for (int j = 0; j < 4; j++) { o0[j] = b2a; o1[j] = b2b; }
#pragma unroll 8
        for (int k = 0; k < 64; k += 2) {
            float2 w0 = *reinterpret_cast<const float2*>(&sU2[k * 64 + 2 * lane]);
            float2 w1 = *reinterpret_cast<const float2*>(&sU2[(k + 1) * 64 + 2 * lane]);
#pragma unroll
            for (int j = 0; j < 4; j++) {
                float2 v = *reinterpret_cast<const float2*>(&sbw[j * 64 + k]);
                o0[j] += v.x * w0.x + v.y * w1.x;
                o1[j] += v.x * w0.y + v.y * w1.y;
            }
        }
#pragma unroll
        for (int j = 0; j < 4; j++) {
            if (j < nv) {
                float2 xr = *reinterpret_cast<const float2*>(&sxw[j * 64 + 2 * lane]);
                float v0 = fmaxf(o0[j] + xr.x, 0.f);
                float v1 = fmaxf(o1[j] + xr.y, 0.f);
                float2 t; t.x = v0; t.y = v1;
                *reinterpret_cast<float2*>(&g_x[(long)(base + j) * 64 + 2 * lane]) = t;
                m0 = fmaxf(m0, v0);
                m1 = fmaxf(m1, v1);
            }
        }
        __syncwarp();
    }
    if (do_max) {  // post-relu x >= 0, so uint compare == float compare
        atomicMax(reinterpret_cast<unsigned*>(&g_mx[2 * lane]), __float_as_uint(m0));
        atomicMax(reinterpret_cast<unsigned*>(&g_mx[2 * lane + 1]), __float_as_uint(m1));
    }
}

// ---------------- head: out = max_x @ head_W + head_b -----------------------
__global__ void k_head(const float* __restrict__ hW, const float* __restrict__ hb,
                       float* __restrict__ out) {
    int t = threadIdx.x;
    float v = g_mx[t] * hW[t];
#pragma unroll
    for (int o = 16; o > 0; o >>= 1) v += __shfl_xor_sync(0xffffffffu, v, o);
    __shared__ float s[2];
    if ((t & 31) == 0) s[t >> 5] = v;
    __syncthreads();
    if (t == 0) out[0] = s[0] + s[1] + hb[0];
}

// ---------------- launch ----------------------------------------------------
extern "C" void kernel_launch(void* const* d_in, const int* in_sizes, int n_in,
                              void* d_out, int out_size) {
    const float* nf = (const float*)d_in[0];
    const int* ei = (const int*)d_in[1];
    const float* ew = (const float*)d_in[2];
    const float* embW = (const float*)d_in[3];
    const float* embB = (const float*)d_in[4];
    const float* msgW1 = (const float*)d_in[5];
    const float* msgB1 = (const float*)d_in[6];
    const float* msgW2 = (const float*)d_in[7];
    const float* msgB2 = (const float*)d_in[8];
    const float* attW1 = (const float*)d_in[9];
    const float* attB1 = (const float*)d_in[10];
    const float* attW2 = (const float*)d_in[11];
    const float* attB2 = (const float*)d_in[12];
    const float* updW1 = (const float*)d_in[13];
    const float* updB1 = (const float*)d_in[14];
    const float* updW2 = (const float*)d_in[15];
    const float* updB2 = (const float*)d_in[16];
    const float* headW = (const float*)d_in[17];
    const float* headB = (const float*)d_in[18];
    float* out = (float*)d_out;

    int n = in_sizes[0] / NF;
    int ne = in_sizes[2];
    const int* row = ei;
    const int* col = ei + ne;

    cudaFuncSetAttribute(k_pre, cudaFuncAttributeMaxDynamicSharedMemorySize, 57344);
    cudaFuncSetAttribute(k_update, cudaFuncAttributeMaxDynamicSharedMemorySize, 81920);

    k_embed<<<1184, 256>>>(nf, embW, embB, n);
    for (int l = 0; l < 2; l++) {
        k_zero<<<512, 256>>>(n);
        k_pre<<<592, 256, 57344>>>(msgW1 + l * 128 * 64, attW1 + l * 128 * 32,
                                   msgB1 + l * 64, attB1 + l * 32, n);
        k_edge<<<444, 256>>>(row, col, ew, attW2 + l * 32, attB2 + l, ne);
        k_update<<<296, 256, 81920>>>(msgW2 + l * 64 * 64, msgB2 + l * 64,
                                      updW1 + l * 128 * 64, updB1 + l * 64,
                                      updW2 + l * 64 * 64, updB2 + l * 64, n,
                                      (l == 1) ? 1 : 0);
    }
    k_head<<<1, 64>>>(headW, headB, out);
}

// round 5
// speedup vs baseline: 2.6711x; 1.6068x over previous
#include <cuda_runtime.h>
#include <cuda_bf16.h>
#include <cuda_fp16.h>
#include <cstdint>

#define NMAX 100000
#define EMAX 1600000
#define H 64
#define NF 18

// ---------------- scratch (device globals; no allocations allowed) ----------
__device__ __align__(128) float g_x[NMAX * 64];
__device__ __align__(128) __half g_PRh[NMAX * 96];  // [msg rowpart+b 64 | att rowpart+b 32]
__device__ __align__(128) __half g_PCh[NMAX * 96];  // [msg colpart 64 | att colpart 32]
__device__ __align__(128) float g_S[NMAX * 64];     // segment_sum(fw * h1)
__device__ __align__(128) float g_sumfw[NMAX];
__device__ __align__(128) float g_mx[64];

// ---------------- zero scratch ----------------
__global__ void k_zero(int n) {
    int i = blockIdx.x * blockDim.x + threadIdx.x;
    int stride = gridDim.x * blockDim.x;
    int tot = n * 64;
    for (int j = i; j < tot; j += stride) g_S[j] = 0.f;
    for (int j = i; j < n; j += stride) g_sumfw[j] = 0.f;
    if (i < 64) g_mx[i] = 0.f;
}

// ---------------- embed: x = relu(nf @ W + b), warp per node ----------------
__global__ __launch_bounds__(256) void k_embed(const float* __restrict__ nf,
                                               const float* __restrict__ W,
                                               const float* __restrict__ b, int n) {
    __shared__ float sW[NF * 64];
    __shared__ float sb[64];
    int tid = threadIdx.x;
    for (int i = tid; i < NF * 64; i += blockDim.x) sW[i] = W[i];
    if (tid < 64) sb[tid] = b[tid];
    __syncthreads();
    int warp = tid >> 5, lane = tid & 31;
    for (int node = blockIdx.x * 8 + warp; node < n; node += gridDim.x * 8) {
        float v = (lane < NF) ? nf[(long)node * NF + lane] : 0.f;
        float a0 = sb[2 * lane], a1 = sb[2 * lane + 1];
#pragma unroll
        for (int k = 0; k < NF; k++) {
            float xv = __shfl_sync(0xffffffffu, v, k);
            a0 += xv * sW[k * 64 + 2 * lane];
            a1 += xv * sW[k * 64 + 2 * lane + 1];
        }
        float2 r;
        r.x = fmaxf(a0, 0.f);
        r.y = fmaxf(a1, 0.f);
        *reinterpret_cast<float2*>(&g_x[(long)node * 64 + 2 * lane]) = r;
    }
}

// ---------------- per-layer precompute: PR/PC node GEMMs, 4 nodes/warp ------
// PR[n] = x[n]@msgW1[0:64] + msgb1 (64) | x[n]@attW1[0:64] + attb1 (32)   (fp16)
// PC[n] = x[n]@msgW1[64:128]       (64) | x[n]@attW1[64:128]       (32)   (fp16)
__global__ __launch_bounds__(256) void k_pre(const float* __restrict__ mW1,
                                             const float* __restrict__ aW1,
                                             const float* __restrict__ mb1,
                                             const float* __restrict__ ab1, int n) {
    extern __shared__ float dsm[];
    float* sM = dsm;             // 128*64 = 8192 floats
    float* sA = dsm + 8192;      // 128*32 = 4096 floats
    float* sx = dsm + 12288;     // 8 warps * 256 floats
    int tid = threadIdx.x;
    for (int i = tid; i < 8192; i += 256) sM[i] = mW1[i];
    for (int i = tid; i < 4096; i += 256) sA[i] = aW1[i];
    __syncthreads();
    int warp = tid >> 5, lane = tid & 31;
    float* sxw = sx + warp * 256;
    float bm0 = mb1[2 * lane], bm1 = mb1[2 * lane + 1], ba = ab1[lane];

    for (int base = (blockIdx.x * 8 + warp) * 4; base < n; base += gridDim.x * 32) {
        int nv = min(4, n - base);
        if (nv == 4) {
            const float4* src = reinterpret_cast<const float4*>(&g_x[(long)base * 64]);
            reinterpret_cast<float4*>(sxw)[lane] = src[lane];
            reinterpret_cast<float4*>(sxw)[lane + 32] = src[lane + 32];
        } else {
            for (int i = lane; i < 256; i += 32)
                sxw[i] = (i < nv * 64) ? g_x[(long)base * 64 + i] : 0.f;
        }
        __syncwarp();

        float pr0[4], pr1[4], pc0[4], pc1[4], ar[4], ac[4];
#pragma unroll
        for (int j = 0; j < 4; j++) {
            pr0[j] = bm0; pr1[j] = bm1; pc0[j] = 0.f; pc1[j] = 0.f;
            ar[j] = ba; ac[j] = 0.f;
        }
#pragma unroll 8
        for (int k = 0; k < 64; k += 2) {
            float2 wma0 = *reinterpret_cast<const float2*>(&sM[k * 64 + 2 * lane]);
            float2 wma1 = *reinterpret_cast<const float2*>(&sM[(k + 1) * 64 + 2 * lane]);
            float2 wmb0 = *reinterpret_cast<const float2*>(&sM[(64 + k) * 64 + 2 * lane]);
            float2 wmb1 = *reinterpret_cast<const float2*>(&sM[(65 + k) * 64 + 2 * lane]);
            float wa0 = sA[k * 32 + lane], wa1 = sA[(k + 1) * 32 + lane];
            float wc0 = sA[(64 + k) * 32 + lane], wc1 = sA[(65 + k) * 32 + lane];
#pragma unroll
            for (int j = 0; j < 4; j++) {
                float2 xv = *reinterpret_cast<const float2*>(&sxw[j * 64 + k]);
                pr0[j] += xv.x * wma0.x + xv.y * wma1.x;
                pr1[j] += xv.x * wma0.y + xv.y * wma1.y;
                pc0[j] += xv.x * wmb0.x + xv.y * wmb1.x;
                pc1[j] += xv.x * wmb0.y + xv.y * wmb1.y;
                ar[j] += xv.x * wa0 + xv.y * wa1;
                ac[j] += xv.x * wc0 + xv.y * wc1;
            }
        }
#pragma unroll
        for (int j = 0; j < 4; j++) {
            if (j < nv) {
                size_t o = (size_t)(base + j) * 96;
                reinterpret_cast<__half2*>(g_PRh + o)[lane] = __floats2half2_rn(pr0[j], pr1[j]);
                g_PRh[o + 64 + lane] = __float2half_rn(ar[j]);
                reinterpret_cast<__half2*>(g_PCh + o)[lane] = __floats2half2_rn(pc0[j], pc1[j]);
                g_PCh[o + 64 + lane] = __float2half_rn(ac[j]);
            }
        }
        __syncwarp();
    }
}

// ---------------- edge kernel: half-warp per edge, fp16 gathers -------------
// lane hl (0..15) of each half-warp: att features (2hl,2hl+1), msg features
// (4hl..4hl+3). red.v4 straight from registers.
__global__ __launch_bounds__(128) void k_edge(const int* __restrict__ row,
                                              const int* __restrict__ col,
                                              const float* __restrict__ ew,
                                              const float* __restrict__ aW2,
                                              const float* __restrict__ ab2, int ne) {
    __shared__ float s_aw2[32];
    if (threadIdx.x < 32) s_aw2[threadIdx.x] = aW2[threadIdx.x];
    __syncthreads();
    int warpsPerBlk = blockDim.x >> 5;
    int W = gridDim.x * warpsPerBlk;
    int w = blockIdx.x * warpsPerBlk + (threadIdx.x >> 5);
    int hl = threadIdx.x & 15;
    int half = (threadIdx.x >> 4) & 1;
    float2 aw;
    aw.x = s_aw2[2 * hl];
    aw.y = s_aw2[2 * hl + 1];
    float ab2v = __ldg(ab2);
    int S = 2 * W;
    const __half2 z2 = __float2half2_rn(0.f);

    for (int eb = 2 * w; eb < ne; eb += 2 * S) {
        int e0 = eb + half;
        int e1 = e0 + S;
        bool v0 = e0 < ne;
        bool v1 = e1 < ne;
        int e0c = v0 ? e0 : 0;
        int e1c = v1 ? e1 : 0;
        int r0 = row[e0c], c0 = col[e0c];
        int r1 = row[e1c], c1 = col[e1c];
        float w0 = ew[e0c], w1 = ew[e1c];
        const __half2* pr0 = reinterpret_cast<const __half2*>(g_PRh + (size_t)r0 * 96);
        const __half2* pc0 = reinterpret_cast<const __half2*>(g_PCh + (size_t)c0 * 96);
        const __half2* pr1 = reinterpret_cast<const __half2*>(g_PRh + (size_t)r1 * 96);
        const __half2* pc1 = reinterpret_cast<const __half2*>(g_PCh + (size_t)c1 * 96);

        // attention partial (2 features per lane), reduce over 16 lanes
        __half2 a0h = __hmax2(__hadd2(pr0[32 + hl], pc0[32 + hl]), z2);
        __half2 a1h = __hmax2(__hadd2(pr1[32 + hl], pc1[32 + hl]), z2);
        float2 a0f = __half22float2(a0h);
        float2 a1f = __half22float2(a1h);
        float t0 = a0f.x * aw.x + a0f.y * aw.y;
        float t1 = a1f.x * aw.x + a1f.y * aw.y;
#pragma unroll
        for (int o = 8; o > 0; o >>= 1) {
            t0 += __shfl_xor_sync(0xffffffffu, t0, o);
            t1 += __shfl_xor_sync(0xffffffffu, t1, o);
        }
        float fw0 = w0 / (1.f + __expf(-(t0 + ab2v)));
        float fw1 = w1 / (1.f + __expf(-(t1 + ab2v)));

        // message features (4 per lane)
        __half2 m00 = __hmax2(__hadd2(pr0[2 * hl], pc0[2 * hl]), z2);
        __half2 m01 = __hmax2(__hadd2(pr0[2 * hl + 1], pc0[2 * hl + 1]), z2);
        __half2 m10 = __hmax2(__hadd2(pr1[2 * hl], pc1[2 * hl]), z2);
        __half2 m11 = __hmax2(__hadd2(pr1[2 * hl + 1], pc1[2 * hl + 1]), z2);
        float2 f00 = __half22float2(m00);
        float2 f01 = __half22float2(m01);
        float2 f10 = __half22float2(m10);
        float2 f11 = __half22float2(m11);

        if (v0) {
            float* d0 = &g_S[(size_t)c0 * 64 + 4 * hl];
            asm volatile("red.global.add.v4.f32 [%0], {%1,%2,%3,%4};" ::"l"(d0),
                         "f"(f00.x * fw0), "f"(f00.y * fw0), "f"(f01.x * fw0),
                         "f"(f01.y * fw0)
                         : "memory");
            if (hl == 0) atomicAdd(&g_sumfw[c0], fw0);
        }
        if (v1) {
            float* d1 = &g_S[(size_t)c1 * 64 + 4 * hl];
            asm volatile("red.global.add.v4.f32 [%0], {%1,%2,%3,%4};" ::"l"(d1),
                         "f"(f10.x * fw1), "f"(f10.y * fw1), "f"(f11.x * fw1),
                         "f"(f11.y * fw1)
                         : "memory");
            if (hl == 0) atomicAdd(&g_sumfw[c1], fw1);
        }
    }
}

// ---------------- fused update: agg=(S@W2+sumfw*b2)/norm, upd MLP, residual,
//                  relu, optional max. 4 nodes per warp. ---------------------
__global__ __launch_bounds__(256) void k_update(const float* __restrict__ W2,
                                                const float* __restrict__ b2,
                                                const float* __restrict__ U1,
                                                const float* __restrict__ ub1,
                                                const float* __restrict__ U2,
                                                const float* __restrict__ ub2, int n,
                                                int do_max) {
    extern __shared__ float dsm[];
    float* sW2 = dsm;            // 4096
    float* sU1 = dsm + 4096;     // 8192
    float* sU2 = dsm + 12288;    // 4096
    float* sx = dsm + 16384;     // 8*256
    float* sB = dsm + 18432;     // 8*256 (S -> a -> h)
    int tid = threadIdx.x;
    for (int i = tid; i < 4096; i += 256) sW2[i] = W2[i];
    for (int i = tid; i < 8192; i += 256) sU1[i] = U1[i];
    for (int i = tid; i < 4096; i += 256) sU2[i] = U2[i];
    __syncthreads();
    int warp = tid >> 5, lane = tid & 31;
    float* sxw = sx + warp * 256;
    float* sbw = sB + warp * 256;
    float bb2a = b2[2 * lane], bb2b = b2[2 * lane + 1];
    float b1a = ub1[2 * lane], b1b = ub1[2 * lane + 1];
    float b2a = ub2[2 * lane], b2b = ub2[2 * lane + 1];
    float m0 = 0.f, m1 = 0.f;

    for (int base = (blockIdx.x * 8 + warp) * 4; base < n; base += gridDim.x * 32) {
        int nv = min(4, n - base);
        if (nv == 4) {
            const float4* srcx = reinterpret_cast<const float4*>(&g_x[(long)base * 64]);
            const float4* srcs = reinterpret_cast<const float4*>(&g_S[(long)base * 64]);
            reinterpret_cast<float4*>(sxw)[lane] = srcx[lane];
            reinterpret_cast<float4*>(sxw)[lane + 32] = srcx[lane + 32];
            reinterpret_cast<float4*>(sbw)[lane] = srcs[lane];
            reinterpret_cast<float4*>(sbw)[lane + 32] = srcs[lane + 32];
        } else {
            for (int i = lane; i < 256; i += 32) {
                sxw[i] = (i < nv * 64) ? g_x[(long)base * 64 + i] : 0.f;
                sbw[i] = (i < nv * 64) ? g_S[(long)base * 64 + i] : 0.f;
            }
        }
        __syncwarp();

        float sf[4], inv[4];
#pragma unroll
        for (int j = 0; j < 4; j++) {
            sf[j] = (j < nv) ? g_sumfw[base + j] : 1.f;
            inv[j] = 1.f / fmaxf(sf[j], 1e-6f);
        }
        // Phase 1: a = (S@W2 + sumfw*b2) / norm
        float a0[4], a1[4];
#pragma unroll
        for (int j = 0; j < 4; j++) { a0[j] = sf[j] * bb2a; a1[j] = sf[j] * bb2b; }
#pragma unroll 8
        for (int k = 0; k < 64; k += 2) {
            float2 w0 = *reinterpret_cast<const float2*>(&sW2[k * 64 + 2 * lane]);
            float2 w1 = *reinterpret_cast<const float2*>(&sW2[(k + 1) * 64 + 2 * lane]);
#pragma unroll
            for (int j = 0; j < 4; j++) {
                float2 v = *reinterpret_cast<const float2*>(&sbw[j * 64 + k]);
                a0[j] += v.x * w0.x + v.y * w1.x;
                a1[j] += v.x * w0.y + v.y * w1.y;
            }
        }
#pragma unroll
        for (int j = 0; j < 4; j++) { a0[j] *= inv[j]; a1[j] *= inv[j]; }
        __syncwarp();
#pragma unroll
        for (int j = 0; j < 4; j++) {
            float2 t; t.x = a0[j]; t.y = a1[j];
            *reinterpret_cast<float2*>(&sbw[j * 64 + 2 * lane]) = t;
        }
        __syncwarp();

        // Phase 2: h = relu(x@U1[0:64] + a@U1[64:128] + b1)
        float h0[4], h1[4];
#pragma unroll
        for (int j = 0; j < 4; j++) { h0[j] = b1a; h1[j] = b1b; }
#pragma unroll 8
        for (int k = 0; k < 64; k += 2) {
            float2 w0 = *reinterpret_cast<const float2*>(&sU1[k * 64 + 2 * lane]);
            float2 w1 = *reinterpret_cast<const float2*>(&sU1[(k + 1) * 64 + 2 * lane]);
#pragma unroll
            for (int j = 0; j < 4; j++) {
                float2 v = *reinterpret_cast<const float2*>(&sxw[j * 64 + k]);
                h0[j] += v.x * w0.x + v.y * w1.x;
                h1[j] += v.x * w0.y + v.y * w1.y;
            }
        }
#pragma unroll 8
        for (int k = 0; k < 64; k += 2) {
            float2 w0 = *reinterpret_cast<const float2*>(&sU1[(64 + k) * 64 + 2 * lane]);
            float2 w1 = *reinterpret_cast<const float2*>(&sU1[(65 + k) * 64 + 2 * lane]);
#pragma unroll
            for (int j = 0; j < 4; j++) {
                float2 v = *reinterpret_cast<const float2*>(&sbw[j * 64 + k]);
                h0[j] += v.x * w0.x + v.y * w1.x;
                h1[j] += v.x * w0.y + v.y * w1.y;
            }
        }
#pragma unroll
        for (int j = 0; j < 4; j++) {
            h0[j] = fmaxf(h0[j], 0.f);
            h1[j] = fmaxf(h1[j], 0.f);
        }
        __syncwarp();
#pragma unroll
        for (int j = 0; j < 4; j++) {
            float2 t; t.x = h0[j]; t.y = h1[j];
            *reinterpret_cast<float2*>(&sbw[j * 64 + 2 * lane]) = t;
        }
        __syncwarp();

        // Phase 3: o = relu(h@U2 + b2 + x)
        float o0[4], o1[4];
#pragma unroll
        for (int j = 0; j < 4; j++) { o0[j] = b2a; o1[j] = b2b; }
#pragma unroll 8
        for (int k = 0; k < 64; k += 2) {
            float2 w0 = *reinterpret_cast<const float2*>(&sU2[k * 64 + 2 * lane]);
            float2 w1 = *reinterpret_cast<const float2*>(&sU2[(k + 1) * 64 + 2 * lane]);
#pragma unroll
            for (int j = 0; j < 4; j++) {
                float2 v = *reinterpret_cast<const float2*>(&sbw[j * 64 + k]);
                o0[j] += v.x * w0.x + v.y * w1.x;
                o1[j] += v.x * w0.y + v.y * w1.y;
            }
        }
#pragma unroll
        for (int j = 0; j < 4; j++) {
            if (j < nv) {
                float2 xr = *reinterpret_cast<const float2*>(&sxw[j * 64 + 2 * lane]);
                float v0 = fmaxf(o0[j] + xr.x, 0.f);
                float v1 = fmaxf(o1[j] + xr.y, 0.f);
                float2 t; t.x = v0; t.y = v1;
                *reinterpret_cast<float2*>(&g_x[(long)(base + j) * 64 + 2 * lane]) = t;
                m0 = fmaxf(m0, v0);
                m1 = fmaxf(m1, v1);
            }
        }
        __syncwarp();
    }
    if (do_max) {  // post-relu x >= 0, so uint compare == float compare
        atomicMax(reinterpret_cast<unsigned*>(&g_mx[2 * lane]), __float_as_uint(m0));
        atomicMax(reinterpret_cast<unsigned*>(&g_mx[2 * lane + 1]), __float_as_uint(m1));
    }
}

// ---------------- head: out = max_x @ head_W + head_b -----------------------
__global__ void k_head(const float* __restrict__ hW, const float* __restrict__ hb,
                       float* __restrict__ out) {
    int t = threadIdx.x;
    float v = g_mx[t] * hW[t];
#pragma unroll
    for (int o = 16; o > 0; o >>= 1) v += __shfl_xor_sync(0xffffffffu, v, o);
    __shared__ float s[2];
    if ((t & 31) == 0) s[t >> 5] = v;
    __syncthreads();
    if (t == 0) out[0] = s[0] + s[1] + hb[0];
}

// ---------------- launch ----------------------------------------------------
extern "C" void kernel_launch(void* const* d_in, const int* in_sizes, int n_in,
                              void* d_out, int out_size) {
    const float* nf = (const float*)d_in[0];
    const int* ei = (const int*)d_in[1];
    const float* ew = (const float*)d_in[2];
    const float* embW = (const float*)d_in[3];
    const float* embB = (const float*)d_in[4];
    const float* msgW1 = (const float*)d_in[5];
    const float* msgB1 = (const float*)d_in[6];
    const float* msgW2 = (const float*)d_in[7];
    const float* msgB2 = (const float*)d_in[8];
    const float* attW1 = (const float*)d_in[9];
    const float* attB1 = (const float*)d_in[10];
    const float* attW2 = (const float*)d_in[11];
    const float* attB2 = (const float*)d_in[12];
    const float* updW1 = (const float*)d_in[13];
    const float* updB1 = (const float*)d_in[14];
    const float* updW2 = (const float*)d_in[15];
    const float* updB2 = (const float*)d_in[16];
    const float* headW = (const float*)d_in[17];
    const float* headB = (const float*)d_in[18];
    float* out = (float*)d_out;

    int n = in_sizes[0] / NF;
    int ne = in_sizes[2];
    const int* row = ei;
    const int* col = ei + ne;

    cudaFuncSetAttribute(k_pre, cudaFuncAttributeMaxDynamicSharedMemorySize, 57344);
    cudaFuncSetAttribute(k_update, cudaFuncAttributeMaxDynamicSharedMemorySize, 81920);

    k_embed<<<1184, 256>>>(nf, embW, embB, n);
    for (int l = 0; l < 2; l++) {
        k_zero<<<512, 256>>>(n);
        k_pre<<<592, 256, 57344>>>(msgW1 + l * 128 * 64, attW1 + l * 128 * 32,
                                   msgB1 + l * 64, attB1 + l * 32, n);
        k_edge<<<2368, 128>>>(row, col, ew, attW2 + l * 32, attB2 + l, ne);
        k_update<<<296, 256, 81920>>>(msgW2 + l * 64 * 64, msgB2 + l * 64,
                                      updW1 + l * 128 * 64, updB1 + l * 64,
                                      updW2 + l * 64 * 64, updB2 + l * 64, n,
                                      (l == 1) ? 1 : 0);
    }
    k_head<<<1, 64>>>(headW, headB, out);
}

// round 10
// speedup vs baseline: 2.7704x; 1.0372x over previous
#include <cuda_runtime.h>
#include <cuda_bf16.h>
#include <cuda_fp16.h>
#include <cstdint>

#define NMAX 100000
#define NF 18

// helper: reinterpret ushort-pair bits as __half2
__device__ __forceinline__ __half2 u32_as_half2(unsigned u) {
    __half2 h;
    *reinterpret_cast<unsigned*>(&h) = u;
    return h;
}

// ---------------- scratch (device globals; no allocations allowed) ----------
__device__ __align__(128) float g_x[NMAX * 64];
__device__ __align__(128) __half g_PRm[NMAX * 64];  // msg rowpart+b (128B rows)
__device__ __align__(128) __half g_PRa[NMAX * 32];  // att rowpart+b (64B rows)
__device__ __align__(128) __half g_PCm[NMAX * 64];  // msg colpart
__device__ __align__(128) __half g_PCa[NMAX * 32];  // att colpart
__device__ __align__(128) float g_S[NMAX * 64];     // segment_sum(fw * h1)
__device__ __align__(128) float g_sumfw[NMAX];
__device__ __align__(128) float g_mx[64];
__device__ __align__(128) float g_Wc[2 * 4096];     // msgW2 @ updW1b per layer
__device__ __align__(128) float g_bvec[2 * 64];     // msgb2 @ updW1b per layer

// ---------------- k_fuse: Wc = msgW2 @ updW1[64:128], bvec = msgb2 @ updW1b -
__global__ __launch_bounds__(256) void k_fuse(const float* __restrict__ msgW2,
                                              const float* __restrict__ msgB2,
                                              const float* __restrict__ updW1) {
    int l = blockIdx.x, chunk = blockIdx.y;
    __shared__ float sU1b[4096];
    const float* U1b = updW1 + l * 8192 + 4096;
    int tid = threadIdx.x;
    for (int i = tid; i < 4096; i += 256) sU1b[i] = U1b[i];
    __syncthreads();
    const float* W2 = msgW2 + l * 4096;
    int i0 = chunk * 8 + (tid >> 5);
    int o = tid & 31;
    float acc0 = 0.f, acc1 = 0.f;
#pragma unroll 8
    for (int j = 0; j < 64; j++) {
        float w = __ldg(&W2[i0 * 64 + j]);
        acc0 += w * sU1b[j * 64 + o];
        acc1 += w * sU1b[j * 64 + o + 32];
    }
    g_Wc[l * 4096 + i0 * 64 + o] = acc0;
    g_Wc[l * 4096 + i0 * 64 + o + 32] = acc1;
    if (chunk == 0 && tid < 64) {
        float acc = 0.f;
        const float* b2 = msgB2 + l * 64;
#pragma unroll 8
        for (int j = 0; j < 64; j++) acc += __ldg(&b2[j]) * sU1b[j * 64 + tid];
        g_bvec[l * 64 + tid] = acc;
    }
}

// ---------------- embed: x = relu(nf @ W + b) + zero S/sumfw/mx -------------
__global__ __launch_bounds__(256) void k_embed(const float* __restrict__ nf,
                                               const float* __restrict__ W,
                                               const float* __restrict__ b, int n) {
    __shared__ float sW[NF * 64];
    __shared__ float sb[64];
    int tid = threadIdx.x;
    for (int i = tid; i < NF * 64; i += blockDim.x) sW[i] = W[i];
    if (tid < 64) sb[tid] = b[tid];
    __syncthreads();
    // zero scratch (for layer 0 / fresh replay)
    int gtid = blockIdx.x * blockDim.x + tid;
    int gstr = gridDim.x * blockDim.x;
    float4 z4 = make_float4(0.f, 0.f, 0.f, 0.f);
    int q = n * 16;
    for (int i = gtid; i < q; i += gstr) reinterpret_cast<float4*>(g_S)[i] = z4;
    for (int i = gtid; i < n; i += gstr) g_sumfw[i] = 0.f;
    if (gtid < 64) g_mx[gtid] = 0.f;

    int warp = tid >> 5, lane = tid & 31;
    for (int node = blockIdx.x * 8 + warp; node < n; node += gridDim.x * 8) {
        float v = (lane < NF) ? nf[(long)node * NF + lane] : 0.f;
        float a0 = sb[2 * lane], a1 = sb[2 * lane + 1];
#pragma unroll
        for (int k = 0; k < NF; k++) {
            float xv = __shfl_sync(0xffffffffu, v, k);
            a0 += xv * sW[k * 64 + 2 * lane];
            a1 += xv * sW[k * 64 + 2 * lane + 1];
        }
        float2 r;
        r.x = fmaxf(a0, 0.f);
        r.y = fmaxf(a1, 0.f);
        *reinterpret_cast<float2*>(&g_x[(long)node * 64 + 2 * lane]) = r;
    }
}

// ---------------- per-layer precompute: PR/PC node GEMMs, 4 nodes/warp ------
__global__ __launch_bounds__(256) void k_pre(const float* __restrict__ mW1,
                                             const float* __restrict__ aW1,
                                             const float* __restrict__ mb1,
                                             const float* __restrict__ ab1, int n) {
    extern __shared__ float dsm[];
    float* sM = dsm;             // 128*64 = 8192 floats
    float* sA = dsm + 8192;      // 128*32 = 4096 floats
    float* sx = dsm + 12288;     // 8 warps * 256 floats
    int tid = threadIdx.x;
    for (int i = tid; i < 8192; i += 256) sM[i] = mW1[i];
    for (int i = tid; i < 4096; i += 256) sA[i] = aW1[i];
    __syncthreads();
    int warp = tid >> 5, lane = tid & 31;
    float* sxw = sx + warp * 256;
    float bm0 = mb1[2 * lane], bm1 = mb1[2 * lane + 1], ba = ab1[lane];

    for (int base = (blockIdx.x * 8 + warp) * 4; base < n; base += gridDim.x * 32) {
        int nv = min(4, n - base);
        if (nv == 4) {
            const float4* src = reinterpret_cast<const float4*>(&g_x[(long)base * 64]);
            reinterpret_cast<float4*>(sxw)[lane] = src[lane];
            reinterpret_cast<float4*>(sxw)[lane + 32] = src[lane + 32];
        } else {
            for (int i = lane; i < 256; i += 32)
                sxw[i] = (i < nv * 64) ? g_x[(long)base * 64 + i] : 0.f;
        }
        __syncwarp();

        float pr0[4], pr1[4], pc0[4], pc1[4], ar[4], ac[4];
#pragma unroll
        for (int j = 0; j < 4; j++) {
            pr0[j] = bm0; pr1[j] = bm1; pc0[j] = 0.f; pc1[j] = 0.f;
            ar[j] = ba; ac[j] = 0.f;
        }
#pragma unroll 8
        for (int k = 0; k < 64; k += 2) {
            float2 wma0 = *reinterpret_cast<const float2*>(&sM[k * 64 + 2 * lane]);
            float2 wma1 = *reinterpret_cast<const float2*>(&sM[(k + 1) * 64 + 2 * lane]);
            float2 wmb0 = *reinterpret_cast<const float2*>(&sM[(64 + k) * 64 + 2 * lane]);
            float2 wmb1 = *reinterpret_cast<const float2*>(&sM[(65 + k) * 64 + 2 * lane]);
            float wa0 = sA[k * 32 + lane], wa1 = sA[(k + 1) * 32 + lane];
            float wc0 = sA[(64 + k) * 32 + lane], wc1 = sA[(65 + k) * 32 + lane];
#pragma unroll
            for (int j = 0; j < 4; j++) {
                float2 xv = *reinterpret_cast<const float2*>(&sxw[j * 64 + k]);
                pr0[j] += xv.x * wma0.x + xv.y * wma1.x;
                pr1[j] += xv.x * wma0.y + xv.y * wma1.y;
                pc0[j] += xv.x * wmb0.x + xv.y * wmb1.x;
                pc1[j] += xv.x * wmb0.y + xv.y * wmb1.y;
                ar[j] += xv.x * wa0 + xv.y * wa1;
                ac[j] += xv.x * wc0 + xv.y * wc1;
            }
        }
#pragma unroll
        for (int j = 0; j < 4; j++) {
            if (j < nv) {
                size_t nd = (size_t)(base + j);
                reinterpret_cast<__half2*>(g_PRm + nd * 64)[lane] =
                    __floats2half2_rn(pr0[j], pr1[j]);
                g_PRa[nd * 32 + lane] = __float2half_rn(ar[j]);
                reinterpret_cast<__half2*>(g_PCm + nd * 64)[lane] =
                    __floats2half2_rn(pc0[j], pc1[j]);
                g_PCa[nd * 32 + lane] = __float2half_rn(ac[j]);
            }
        }
        __syncwarp();
    }
}

// ---------------- edge kernel: half-warp per edge, aligned fp16 gathers -----
__global__ __launch_bounds__(128) void k_edge(const int* __restrict__ row,
                                              const int* __restrict__ col,
                                              const float* __restrict__ ew,
                                              const float* __restrict__ aW2,
                                              const float* __restrict__ ab2, int ne) {
    __shared__ float s_aw2[32];
    if (threadIdx.x < 32) s_aw2[threadIdx.x] = aW2[threadIdx.x];
    __syncthreads();
    int warpsPerBlk = blockDim.x >> 5;
    int W = gridDim.x * warpsPerBlk;
    int w = blockIdx.x * warpsPerBlk + (threadIdx.x >> 5);
    int hl = threadIdx.x & 15;
    int half = (threadIdx.x >> 4) & 1;
    float2 aw;
    aw.x = s_aw2[2 * hl];
    aw.y = s_aw2[2 * hl + 1];
    float ab2v = __ldg(ab2);
    int S = 2 * W;
    const __half2 z2 = __float2half2_rn(0.f);

    for (int eb = 2 * w; eb < ne; eb += 2 * S) {
        int e0 = eb + half;
        int e1 = e0 + S;
        bool v0 = e0 < ne;
        bool v1 = e1 < ne;
        int e0c = v0 ? e0 : 0;
        int e1c = v1 ? e1 : 0;
        int r0 = row[e0c], c0 = col[e0c];
        int r1 = row[e1c], c1 = col[e1c];
        float w0 = ew[e0c], w1 = ew[e1c];

        uint2 pm0r = *reinterpret_cast<const uint2*>(g_PRm + (size_t)r0 * 64 + 4 * hl);
        uint2 pm0c = *reinterpret_cast<const uint2*>(g_PCm + (size_t)c0 * 64 + 4 * hl);
        uint2 pm1r = *reinterpret_cast<const uint2*>(g_PRm + (size_t)r1 * 64 + 4 * hl);
        uint2 pm1c = *reinterpret_cast<const uint2*>(g_PCm + (size_t)c1 * 64 + 4 * hl);
        __half2 pa0r = *reinterpret_cast<const __half2*>(g_PRa + (size_t)r0 * 32 + 2 * hl);
        __half2 pa0c = *reinterpret_cast<const __half2*>(g_PCa + (size_t)c0 * 32 + 2 * hl);
        __half2 pa1r = *reinterpret_cast<const __half2*>(g_PRa + (size_t)r1 * 32 + 2 * hl);
        __half2 pa1c = *reinterpret_cast<const __half2*>(g_PCa + (size_t)c1 * 32 + 2 * hl);

        // attention partial (2 features per lane), reduce over 16 lanes
        float2 a0f = __half22float2(__hmax2(__hadd2(pa0r, pa0c), z2));
        float2 a1f = __half22float2(__hmax2(__hadd2(pa1r, pa1c), z2));
        float t0 = a0f.x * aw.x + a0f.y * aw.y;
        float t1 = a1f.x * aw.x + a1f.y * aw.y;
#pragma unroll
        for (int o = 8; o > 0; o >>= 1) {
            t0 += __shfl_xor_sync(0xffffffffu, t0, o);
            t1 += __shfl_xor_sync(0xffffffffu, t1, o);
        }
        float fw0 = w0 / (1.f + __expf(-(t0 + ab2v)));
        float fw1 = w1 / (1.f + __expf(-(t1 + ab2v)));

        // message features (4 per lane)
        float2 f00 = __half22float2(__hmax2(__hadd2(u32_as_half2(pm0r.x), u32_as_half2(pm0c.x)), z2));
        float2 f01 = __half22float2(__hmax2(__hadd2(u32_as_half2(pm0r.y), u32_as_half2(pm0c.y)), z2));
        float2 f10 = __half22float2(__hmax2(__hadd2(u32_as_half2(pm1r.x), u32_as_half2(pm1c.x)), z2));
        float2 f11 = __half22float2(__hmax2(__hadd2(u32_as_half2(pm1r.y), u32_as_half2(pm1c.y)), z2));

        if (v0) {
            float* d0 = &g_S[(size_t)c0 * 64 + 4 * hl];
            asm volatile("red.global.add.v4.f32 [%0], {%1,%2,%3,%4};" ::"l"(d0),
                         "f"(f00.x * fw0), "f"(f00.y * fw0), "f"(f01.x * fw0),
                         "f"(f01.y * fw0)
                         : "memory");
            if (hl == 0) atomicAdd(&g_sumfw[c0], fw0);
        }
        if (v1) {
            float* d1 = &g_S[(size_t)c1 * 64 + 4 * hl];
            asm volatile("red.global.add.v4.f32 [%0], {%1,%2,%3,%4};" ::"l"(d1),
                         "f"(f10.x * fw1), "f"(f10.y * fw1), "f"(f11.x * fw1),
                         "f"(f11.y * fw1)
                         : "memory");
            if (hl == 0) atomicAdd(&g_sumfw[c1], fw1);
        }
    }
}

// ---------------- fused update with Wc fold + rezero ------------------------
// h = relu(x@U1a + b1 + inv*(S@Wc) + (sumfw*inv)*bvec); o = relu(h@U2 + b2 + x)
__global__ __launch_bounds__(256) void k_update(int l,
                                                const float* __restrict__ U1,
                                                const float* __restrict__ ub1,
                                                const float* __restrict__ U2,
                                                const float* __restrict__ ub2, int n,
                                                int do_max) {
    extern __shared__ float dsm[];
    float* sWc = dsm;             // 4096
    float* sU1 = dsm + 4096;      // 4096 (x-part rows only)
    float* sU2 = dsm + 8192;      // 4096
    float* sbv = dsm + 12288;     // 64
    float* sx = dsm + 12352;      // 8*256
    float* sS = dsm + 14400;      // 8*256
    int tid = threadIdx.x;
    const float* Wc = g_Wc + l * 4096;
    for (int i = tid; i < 4096; i += 256) {
        sWc[i] = Wc[i];
        sU1[i] = U1[i];
        sU2[i] = U2[i];
    }
    if (tid < 64) sbv[tid] = g_bvec[l * 64 + tid];
    __syncthreads();
    int warp = tid >> 5, lane = tid & 31;
    float* sxw = sx + warp * 256;
    float* sbw = sS + warp * 256;
    float bv0 = sbv[2 * lane], bv1 = sbv[2 * lane + 1];
    float b1a = ub1[2 * lane], b1b = ub1[2 * lane + 1];
    float b2a = ub2[2 * lane], b2b = ub2[2 * lane + 1];
    float m0 = 0.f, m1 = 0.f;
    float4 z4 = make_float4(0.f, 0.f, 0.f, 0.f);

    for (int base = (blockIdx.x * 8 + warp) * 4; base < n; base += gridDim.x * 32) {
        int nv = min(4, n - base);
        if (nv == 4) {
            const float4* srcx = reinterpret_cast<const float4*>(&g_x[(size_t)base * 64]);
            float4* srcs = reinterpret_cast<float4*>(&g_S[(size_t)base * 64]);
            float4 s0 = srcs[lane], s1 = srcs[lane + 32];
            reinterpret_cast<float4*>(sxw)[lane] = srcx[lane];
            reinterpret_cast<float4*>(sxw)[lane + 32] = srcx[lane + 32];
            reinterpret_cast<float4*>(sbw)[lane] = s0;
            reinterpret_cast<float4*>(sbw)[lane + 32] = s1;
            srcs[lane] = z4;          // rezero for next layer / next replay
            srcs[lane + 32] = z4;
        } else {
            for (int i = lane; i < 256; i += 32) {
                bool in = (i < nv * 64);
                sxw[i] = in ? g_x[(size_t)base * 64 + i] : 0.f;
                sbw[i] = in ? g_S[(size_t)base * 64 + i] : 0.f;
                if (in) g_S[(size_t)base * 64 + i] = 0.f;
            }
        }
        __syncwarp();

        float sf[4], inv[4];
#pragma unroll
        for (int j = 0; j < 4; j++) {
            sf[j] = (j < nv) ? g_sumfw[base + j] : 1.f;
            inv[j] = 1.f / fmaxf(sf[j], 1e-6f);
        }
        __syncwarp();
        if (lane < nv) g_sumfw[base + lane] = 0.f;

        // Phase 1: g = S @ Wc
        float g0[4], g1[4];
#pragma unroll
        for (int j = 0; j < 4; j++) { g0[j] = 0.f; g1[j] = 0.f; }
#pragma unroll 8
        for (int k = 0; k < 64; k += 2) {
            float2 w0 = *reinterpret_cast<const float2*>(&sWc[k * 64 + 2 * lane]);
            float2 w1 = *reinterpret_cast<const float2*>(&sWc[(k + 1) * 64 + 2 * lane]);
#pragma unroll
            for (int j = 0; j < 4; j++) {
                float2 v = *reinterpret_cast<const float2*>(&sbw[j * 64 + k]);
                g0[j] += v.x * w0.x + v.y * w1.x;
                g1[j] += v.x * w0.y + v.y * w1.y;
            }
        }

        // Phase 2: h = relu(x@U1a + b1 + inv*g + (sf*inv)*bvec)
        float h0[4], h1[4];
#pragma unroll
        for (int j = 0; j < 4; j++) {
            float r = sf[j] * inv[j];
            h0[j] = b1a + inv[j] * g0[j] + r * bv0;
            h1[j] = b1b + inv[j] * g1[j] + r * bv1;
        }
#pragma unroll 8
        for (int k = 0; k < 64; k += 2) {
            float2 w0 = *reinterpret_cast<const float2*>(&sU1[k * 64 + 2 * lane]);
            float2 w1 = *reinterpret_cast<const float2*>(&sU1[(k + 1) * 64 + 2 * lane]);
#pragma unroll
            for (int j = 0; j < 4; j++) {
                float2 v = *reinterpret_cast<const float2*>(&sxw[j * 64 + k]);
                h0[j] += v.x * w0.x + v.y * w1.x;
                h1[j] += v.x * w0.y + v.y * w1.y;
            }
        }
#pragma unroll
        for (int j = 0; j < 4; j++) {
            h0[j] = fmaxf(h0[j], 0.f);
            h1[j] = fmaxf(h1[j], 0.f);
        }
        __syncwarp();
#pragma unroll
        for (int j = 0; j < 4; j++) {
            float2 t; t.x = h0[j]; t.y = h1[j];
            *reinterpret_cast<float2*>(&sbw[j * 64 + 2 * lane]) = t;
        }
        __syncwarp();

        // Phase 3: o = relu(h@U2 + b2 + x)
        float o0[4], o1[4];
#pragma unroll
        for (int j = 0; j < 4; j++) { o0[j] = b2a; o1[j] = b2b; }
#pragma unroll 8
        for (int k = 0; k < 64; k += 2) {
            float2 w0 = *reinterpret_cast<const float2*>(&sU2[k * 64 + 2 * lane]);
            float2 w1 = *reinterpret_cast<const float2*>(&sU2[(k + 1) * 64 + 2 * lane]);
#pragma unroll
            for (int j = 0; j < 4; j++) {
                float2 v = *reinterpret_cast<const float2*>(&sbw[j * 64 + k]);
                o0[j] += v.x * w0.x + v.y * w1.x;
                o1[j] += v.x * w0.y + v.y * w1.y;
            }
        }
#pragma unroll
        for (int j = 0; j < 4; j++) {
            if (j < nv) {
                float2 xr = *reinterpret_cast<const float2*>(&sxw[j * 64 + 2 * lane]);
                float v0 = fmaxf(o0[j] + xr.x, 0.f);
                float v1 = fmaxf(o1[j] + xr.y, 0.f);
                float2 t; t.x = v0; t.y = v1;
                *reinterpret_cast<float2*>(&g_x[(size_t)(base + j) * 64 + 2 * lane]) = t;
                m0 = fmaxf(m0, v0);
                m1 = fmaxf(m1, v1);
            }
        }
        __syncwarp();
    }
    if (do_max) {  // post-relu x >= 0, so uint compare == float compare
        atomicMax(reinterpret_cast<unsigned*>(&g_mx[2 * lane]), __float_as_uint(m0));
        atomicMax(reinterpret_cast<unsigned*>(&g_mx[2 * lane + 1]), __float_as_uint(m1));
    }
}

// ---------------- head: out = max_x @ head_W + head_b -----------------------
__global__ void k_head(const float* __restrict__ hW, const float* __restrict__ hb,
                       float* __restrict__ out) {
    int t = threadIdx.x;
    float v = g_mx[t] * hW[t];
#pragma unroll
    for (int o = 16; o > 0; o >>= 1) v += __shfl_xor_sync(0xffffffffu, v, o);
    __shared__ float s[2];
    if ((t & 31) == 0) s[t >> 5] = v;
    __syncthreads();
    if (t == 0) out[0] = s[0] + s[1] + hb[0];
}

// ---------------- launch ----------------------------------------------------
extern "C" void kernel_launch(void* const* d_in, const int* in_sizes, int n_in,
                              void* d_out, int out_size) {
    const float* nf = (const float*)d_in[0];
    const int* ei = (const int*)d_in[1];
    const float* ew = (const float*)d_in[2];
    const float* embW = (const float*)d_in[3];
    const float* embB = (const float*)d_in[4];
    const float* msgW1 = (const float*)d_in[5];
    const float* msgB1 = (const float*)d_in[6];
    const float* msgW2 = (const float*)d_in[7];
    const float* msgB2 = (const float*)d_in[8];
    const float* attW1 = (const float*)d_in[9];
    const float* attB1 = (const float*)d_in[10];
    const float* attW2 = (const float*)d_in[11];
    const float* attB2 = (const float*)d_in[12];
    const float* updW1 = (const float*)d_in[13];
    const float* updB1 = (const float*)d_in[14];
    const float* updW2 = (const float*)d_in[15];
    const float* updB2 = (const float*)d_in[16];
    const float* headW = (const float*)d_in[17];
    const float* headB = (const float*)d_in[18];
    float* out = (float*)d_out;

    int n = in_sizes[0] / NF;
    int ne = in_sizes[2];
    const int* row = ei;
    const int* col = ei + ne;

    cudaFuncSetAttribute(k_pre, cudaFuncAttributeMaxDynamicSharedMemorySize, 57344);
    cudaFuncSetAttribute(k_update, cudaFuncAttributeMaxDynamicSharedMemorySize, 65792);

    k_fuse<<<dim3(2, 8), 256>>>(msgW2, msgB2, updW1);
    k_embed<<<1184, 256>>>(nf, embW, embB, n);
    for (int l = 0; l < 2; l++) {
        k_pre<<<592, 256, 57344>>>(msgW1 + l * 128 * 64, attW1 + l * 128 * 32,
                                   msgB1 + l * 64, attB1 + l * 32, n);
        k_edge<<<2368, 128>>>(row, col, ew, attW2 + l * 32, attB2 + l, ne);
        k_update<<<444, 256, 65792>>>(l, updW1 + l * 128 * 64, updB1 + l * 64,
                                      updW2 + l * 64 * 64, updB2 + l * 64, n,
                                      (l == 1) ? 1 : 0);
    }
    k_head<<<1, 64>>>(headW, headB, out);
}

// round 11
// speedup vs baseline: 3.2301x; 1.1660x over previous
#include <cuda_runtime.h>
#include <cuda_bf16.h>
#include <cuda_fp16.h>
#include <cstdint>

#define NMAX 100000
#define NF 18

// helper: reinterpret u32 bits as __half2
__device__ __forceinline__ __half2 u32_as_half2(unsigned u) {
    __half2 h;
    *reinterpret_cast<unsigned*>(&h) = u;
    return h;
}

__device__ __forceinline__ void ldsm_x4(uint32_t& r0, uint32_t& r1, uint32_t& r2,
                                        uint32_t& r3, uint32_t addr) {
    asm volatile("ldmatrix.sync.aligned.m8n8.x4.shared.b16 {%0,%1,%2,%3}, [%4];"
                 : "=r"(r0), "=r"(r1), "=r"(r2), "=r"(r3)
                 : "r"(addr));
}
__device__ __forceinline__ void ldsm_x2(uint32_t& r0, uint32_t& r1, uint32_t addr) {
    asm volatile("ldmatrix.sync.aligned.m8n8.x2.shared.b16 {%0,%1}, [%2];"
                 : "=r"(r0), "=r"(r1)
                 : "r"(addr));
}
__device__ __forceinline__ void mma16816(float& c0, float& c1, float& c2, float& c3,
                                         uint32_t a0, uint32_t a1, uint32_t a2,
                                         uint32_t a3, uint32_t b0, uint32_t b1) {
    asm volatile(
        "mma.sync.aligned.m16n8k16.row.col.f32.f16.f16.f32 "
        "{%0,%1,%2,%3}, {%4,%5,%6,%7}, {%8,%9}, {%0,%1,%2,%3};"
        : "+f"(c0), "+f"(c1), "+f"(c2), "+f"(c3)
        : "r"(a0), "r"(a1), "r"(a2), "r"(a3), "r"(b0), "r"(b1));
}

// ---------------- scratch (device globals; no allocations allowed) ----------
__device__ __align__(128) float g_x[NMAX * 64];
__device__ __align__(128) __half g_xh[NMAX * 64];   // fp16 shadow of x
__device__ __align__(256) __half g_PR[NMAX * 128];  // [msg 64 | att 32 | pad 32]
__device__ __align__(256) __half g_PC[NMAX * 128];  // [msg 64 | att 32 | pad 32]
__device__ __align__(128) float g_S[NMAX * 64];     // segment_sum(fw * h1)
__device__ __align__(128) float g_sumfw[NMAX];
__device__ __align__(128) float g_mx[64];
__device__ __align__(128) float g_Wc[2 * 4096];     // msgW2 @ updW1b per layer
__device__ __align__(128) float g_bvec[2 * 64];     // msgb2 @ updW1b per layer
__device__ __align__(128) __half g_Wb[2 * 192 * 64];// fused pre-weights, [n][k] fp16
__device__ __align__(128) float g_bias[2 * 192];    // fused pre-bias (0 for PC)

// ---------------- k_wprep: build fused fp16 weight [n][k] + bias ------------
// n 0-63: PR msg (mW1[k][n]), 64-127: PC msg (mW1[64+k][n-64]),
// n 128-159: PR att (aW1[k][n-128]), 160-191: PC att (aW1[64+k][n-160])
__global__ __launch_bounds__(256) void k_wprep(const float* __restrict__ mW1,
                                               const float* __restrict__ aW1,
                                               const float* __restrict__ mb1,
                                               const float* __restrict__ ab1) {
    int l = blockIdx.x;
    int tid = threadIdx.x;
    const float* mW = mW1 + l * 8192;
    const float* aW = aW1 + l * 4096;
    for (int idx = tid; idx < 192 * 64; idx += 256) {
        int nn = idx >> 6, k = idx & 63;
        float v;
        if (nn < 64) v = mW[k * 64 + nn];
        else if (nn < 128) v = mW[(64 + k) * 64 + (nn - 64)];
        else if (nn < 160) v = aW[k * 32 + (nn - 128)];
        else v = aW[(64 + k) * 32 + (nn - 160)];
        g_Wb[l * 12288 + idx] = __float2half_rn(v);
    }
    for (int nn = tid; nn < 192; nn += 256) {
        float b = 0.f;
        if (nn < 64) b = mb1[l * 64 + nn];
        else if (nn >= 128 && nn < 160) b = ab1[l * 32 + (nn - 128)];
        g_bias[l * 192 + nn] = b;
    }
}

// ---------------- k_fuse: Wc = msgW2 @ updW1[64:128], bvec = msgb2 @ updW1b -
__global__ __launch_bounds__(256) void k_fuse(const float* __restrict__ msgW2,
                                              const float* __restrict__ msgB2,
                                              const float* __restrict__ updW1) {
    int l = blockIdx.x, chunk = blockIdx.y;
    __shared__ float sU1b[4096];
    const float* U1b = updW1 + l * 8192 + 4096;
    int tid = threadIdx.x;
    for (int i = tid; i < 4096; i += 256) sU1b[i] = U1b[i];
    __syncthreads();
    const float* W2 = msgW2 + l * 4096;
    int i0 = chunk * 8 + (tid >> 5);
    int o = tid & 31;
    float acc0 = 0.f, acc1 = 0.f;
#pragma unroll 8
    for (int j = 0; j < 64; j++) {
        float w = __ldg(&W2[i0 * 64 + j]);
        acc0 += w * sU1b[j * 64 + o];
        acc1 += w * sU1b[j * 64 + o + 32];
    }
    g_Wc[l * 4096 + i0 * 64 + o] = acc0;
    g_Wc[l * 4096 + i0 * 64 + o + 32] = acc1;
    if (chunk == 0 && tid < 64) {
        float acc = 0.f;
        const float* b2 = msgB2 + l * 64;
#pragma unroll 8
        for (int j = 0; j < 64; j++) acc += __ldg(&b2[j]) * sU1b[j * 64 + tid];
        g_bvec[l * 64 + tid] = acc;
    }
}

// ---------------- embed: x = relu(nf @ W + b) + zero S/sumfw/mx -------------
__global__ __launch_bounds__(256) void k_embed(const float* __restrict__ nf,
                                               const float* __restrict__ W,
                                               const float* __restrict__ b, int n) {
    __shared__ float sW[NF * 64];
    __shared__ float sb[64];
    int tid = threadIdx.x;
    for (int i = tid; i < NF * 64; i += blockDim.x) sW[i] = W[i];
    if (tid < 64) sb[tid] = b[tid];
    __syncthreads();
    int gtid = blockIdx.x * blockDim.x + tid;
    int gstr = gridDim.x * blockDim.x;
    float4 z4 = make_float4(0.f, 0.f, 0.f, 0.f);
    int q = n * 16;
    for (int i = gtid; i < q; i += gstr) reinterpret_cast<float4*>(g_S)[i] = z4;
    for (int i = gtid; i < n; i += gstr) g_sumfw[i] = 0.f;
    if (gtid < 64) g_mx[gtid] = 0.f;

    int warp = tid >> 5, lane = tid & 31;
    for (int node = blockIdx.x * 8 + warp; node < n; node += gridDim.x * 8) {
        float v = (lane < NF) ? nf[(long)node * NF + lane] : 0.f;
        float a0 = sb[2 * lane], a1 = sb[2 * lane + 1];
#pragma unroll
        for (int k = 0; k < NF; k++) {
            float xv = __shfl_sync(0xffffffffu, v, k);
            a0 += xv * sW[k * 64 + 2 * lane];
            a1 += xv * sW[k * 64 + 2 * lane + 1];
        }
        float2 r;
        r.x = fmaxf(a0, 0.f);
        r.y = fmaxf(a1, 0.f);
        *reinterpret_cast<float2*>(&g_x[(size_t)node * 64 + 2 * lane]) = r;
        *reinterpret_cast<__half2*>(&g_xh[(size_t)node * 64 + 2 * lane]) =
            __floats2half2_rn(r.x, r.y);
    }
}

// ---------------- k_pre_mma: PR/PC via tensor cores -------------------------
// [128-node batch] x[128,64]f16 @ Wb[64,192] -> PR/PC (fp16, padded 128 rows)
__global__ __launch_bounds__(256) void k_pre_mma(int l, int n) {
    extern __shared__ __align__(16) unsigned char smraw[];
    __half* sWb = reinterpret_cast<__half*>(smraw);                 // 192*64 halfs
    __half* sx = reinterpret_cast<__half*>(smraw + 24576);          // 128*64 halfs
    float* sbias = reinterpret_cast<float*>(smraw + 24576 + 16384); // 192 floats
    int tid = threadIdx.x;
    // stage Wb (swizzled 16B chunks: c' = c ^ (row&7))
    const uint4* gW = reinterpret_cast<const uint4*>(g_Wb + l * 12288);
    uint4* sW4 = reinterpret_cast<uint4*>(sWb);
    for (int i = tid; i < 1536; i += 256) {
        int r = i >> 3, c = i & 7;
        sW4[r * 8 + (c ^ (r & 7))] = gW[i];
    }
    for (int i = tid; i < 192; i += 256) sbias[i] = g_bias[l * 192 + i];
    uint32_t sx_u = (uint32_t)__cvta_generic_to_shared(sx);
    uint32_t sW_u = (uint32_t)__cvta_generic_to_shared(sWb);
    int warp = tid >> 5, lane = tid & 31;
    int nb = (n + 127) >> 7;

    for (int batch = blockIdx.x; batch < nb; batch += gridDim.x) {
        int base = batch << 7;
        __syncthreads();  // prior compute done (also orders Wb staging, iter 0)
        const uint4* gx = reinterpret_cast<const uint4*>(g_xh + (size_t)base * 64);
        uint4* sx4 = reinterpret_cast<uint4*>(sx);
        for (int i = tid; i < 1024; i += 256) {
            int r = i >> 3, c = i & 7;
            uint4 v = make_uint4(0, 0, 0, 0);
            if (base + r < n) v = gx[i];
            sx4[r * 8 + (c ^ (r & 7))] = v;
        }
        __syncthreads();

        // A fragments: 16 nodes per warp, 4 k-tiles
        uint32_t a[4][4];
        int m0 = warp * 16;
        {
            int grp = lane >> 3, lr = lane & 7;
            int r = m0 + ((grp & 1) << 3) + lr;
            int chalf = grp >> 1;
#pragma unroll
            for (int kb = 0; kb < 4; kb++) {
                int c = kb * 2 + chalf;
                uint32_t addr = sx_u + (uint32_t)((r * 8 + (c ^ (r & 7))) * 16);
                ldsm_x4(a[kb][0], a[kb][1], a[kb][2], a[kb][3], addr);
            }
        }
        int grp2 = (lane >> 3) & 1, lr2 = lane & 7;
        int mlo = base + m0 + (lane >> 2);
        int mhi = mlo + 8;
#pragma unroll 1
        for (int t = 0; t < 24; t++) {
            float c0 = 0.f, c1 = 0.f, c2 = 0.f, c3 = 0.f;
#pragma unroll
            for (int kb = 0; kb < 4; kb++) {
                int nrow = t * 8 + lr2;
                int cch = kb * 2 + grp2;
                uint32_t baddr =
                    sW_u + (uint32_t)((nrow * 8 + (cch ^ (nrow & 7))) * 16);
                uint32_t b0, b1;
                ldsm_x2(b0, b1, baddr);
                mma16816(c0, c1, c2, c3, a[kb][0], a[kb][1], a[kb][2], a[kb][3],
                         b0, b1);
            }
            int nloc = t * 8 + 2 * (lane & 3);
            float bsa = sbias[nloc], bsb = sbias[nloc + 1];
            c0 += bsa; c1 += bsb; c2 += bsa; c3 += bsb;
            __half* dst;
            int off;
            if (t < 8) { dst = g_PR; off = nloc; }
            else if (t < 16) { dst = g_PC; off = nloc - 64; }
            else if (t < 20) { dst = g_PR; off = nloc - 64; }
            else { dst = g_PC; off = nloc - 96; }
            if (mlo < n)
                *reinterpret_cast<__half2*>(dst + (size_t)mlo * 128 + off) =
                    __floats2half2_rn(c0, c1);
            if (mhi < n)
                *reinterpret_cast<__half2*>(dst + (size_t)mhi * 128 + off) =
                    __floats2half2_rn(c2, c3);
        }
    }
}

// ---------------- edge kernel: half-warp per edge, padded aligned rows ------
__global__ __launch_bounds__(128) void k_edge(const int* __restrict__ row,
                                              const int* __restrict__ col,
                                              const float* __restrict__ ew,
                                              const float* __restrict__ aW2,
                                              const float* __restrict__ ab2, int ne) {
    __shared__ float s_aw2[32];
    if (threadIdx.x < 32) s_aw2[threadIdx.x] = aW2[threadIdx.x];
    __syncthreads();
    int warpsPerBlk = blockDim.x >> 5;
    int W = gridDim.x * warpsPerBlk;
    int w = blockIdx.x * warpsPerBlk + (threadIdx.x >> 5);
    int hl = threadIdx.x & 15;
    int half = (threadIdx.x >> 4) & 1;
    float2 aw;
    aw.x = s_aw2[2 * hl];
    aw.y = s_aw2[2 * hl + 1];
    float ab2v = __ldg(ab2);
    int S = 2 * W;
    const __half2 z2 = __float2half2_rn(0.f);

    for (int eb = 2 * w; eb < ne; eb += 2 * S) {
        int e0 = eb + half;
        int e1 = e0 + S;
        bool v0 = e0 < ne;
        bool v1 = e1 < ne;
        int e0c = v0 ? e0 : 0;
        int e1c = v1 ? e1 : 0;
        int r0 = row[e0c], c0 = col[e0c];
        int r1 = row[e1c], c1 = col[e1c];
        float w0 = ew[e0c], w1 = ew[e1c];

        const __half* pr0 = g_PR + (size_t)r0 * 128;
        const __half* pc0 = g_PC + (size_t)c0 * 128;
        const __half* pr1 = g_PR + (size_t)r1 * 128;
        const __half* pc1 = g_PC + (size_t)c1 * 128;

        uint2 pm0r = __ldg(reinterpret_cast<const uint2*>(pr0 + 4 * hl));
        uint2 pm0c = __ldg(reinterpret_cast<const uint2*>(pc0 + 4 * hl));
        uint2 pm1r = __ldg(reinterpret_cast<const uint2*>(pr1 + 4 * hl));
        uint2 pm1c = __ldg(reinterpret_cast<const uint2*>(pc1 + 4 * hl));
        __half2 pa0r = __ldg(reinterpret_cast<const __half2*>(pr0 + 64 + 2 * hl));
        __half2 pa0c = __ldg(reinterpret_cast<const __half2*>(pc0 + 64 + 2 * hl));
        __half2 pa1r = __ldg(reinterpret_cast<const __half2*>(pr1 + 64 + 2 * hl));
        __half2 pa1c = __ldg(reinterpret_cast<const __half2*>(pc1 + 64 + 2 * hl));

        // attention partial (2 features per lane), reduce over 16 lanes
        float2 a0f = __half22float2(__hmax2(__hadd2(pa0r, pa0c), z2));
        float2 a1f = __half22float2(__hmax2(__hadd2(pa1r, pa1c), z2));
        float t0 = a0f.x * aw.x + a0f.y * aw.y;
        float t1 = a1f.x * aw.x + a1f.y * aw.y;
#pragma unroll
        for (int o = 8; o > 0; o >>= 1) {
            t0 += __shfl_xor_sync(0xffffffffu, t0, o);
            t1 += __shfl_xor_sync(0xffffffffu, t1, o);
        }
        float fw0 = w0 / (1.f + __expf(-(t0 + ab2v)));
        float fw1 = w1 / (1.f + __expf(-(t1 + ab2v)));

        // message features (4 per lane)
        float2 f00 = __half22float2(__hmax2(__hadd2(u32_as_half2(pm0r.x), u32_as_half2(pm0c.x)), z2));
        float2 f01 = __half22float2(__hmax2(__hadd2(u32_as_half2(pm0r.y), u32_as_half2(pm0c.y)), z2));
        float2 f10 = __half22float2(__hmax2(__hadd2(u32_as_half2(pm1r.x), u32_as_half2(pm1c.x)), z2));
        float2 f11 = __half22float2(__hmax2(__hadd2(u32_as_half2(pm1r.y), u32_as_half2(pm1c.y)), z2));

        if (v0) {
            float* d0 = &g_S[(size_t)c0 * 64 + 4 * hl];
            asm volatile("red.global.add.v4.f32 [%0], {%1,%2,%3,%4};" ::"l"(d0),
                         "f"(f00.x * fw0), "f"(f00.y * fw0), "f"(f01.x * fw0),
                         "f"(f01.y * fw0)
                         : "memory");
            if (hl == 0) atomicAdd(&g_sumfw[c0], fw0);
        }
        if (v1) {
            float* d1 = &g_S[(size_t)c1 * 64 + 4 * hl];
            asm volatile("red.global.add.v4.f32 [%0], {%1,%2,%3,%4};" ::"l"(d1),
                         "f"(f10.x * fw1), "f"(f10.y * fw1), "f"(f11.x * fw1),
                         "f"(f11.y * fw1)
                         : "memory");
            if (hl == 0) atomicAdd(&g_sumfw[c1], fw1);
        }
    }
}

// ---------------- fused update with Wc fold + rezero + xh shadow ------------
__global__ __launch_bounds__(256) void k_update(int l,
                                                const float* __restrict__ U1,
                                                const float* __restrict__ ub1,
                                                const float* __restrict__ U2,
                                                const float* __restrict__ ub2, int n,
                                                int do_max) {
    extern __shared__ float dsm[];
    float* sWc = dsm;             // 4096
    float* sU1 = dsm + 4096;      // 4096 (x-part rows only)
    float* sU2 = dsm + 8192;      // 4096
    float* sbv = dsm + 12288;     // 64
    float* sx = dsm + 12352;      // 8*256
    float* sS = dsm + 14400;      // 8*256
    int tid = threadIdx.x;
    const float* Wc = g_Wc + l * 4096;
    for (int i = tid; i < 4096; i += 256) {
        sWc[i] = Wc[i];
        sU1[i] = U1[i];
        sU2[i] = U2[i];
    }
    if (tid < 64) sbv[tid] = g_bvec[l * 64 + tid];
    __syncthreads();
    int warp = tid >> 5, lane = tid & 31;
    float* sxw = sx + warp * 256;
    float* sbw = sS + warp * 256;
    float bv0 = sbv[2 * lane], bv1 = sbv[2 * lane + 1];
    float b1a = ub1[2 * lane], b1b = ub1[2 * lane + 1];
    float b2a = ub2[2 * lane], b2b = ub2[2 * lane + 1];
    float m0 = 0.f, m1 = 0.f;
    float4 z4 = make_float4(0.f, 0.f, 0.f, 0.f);

    for (int base = (blockIdx.x * 8 + warp) * 4; base < n; base += gridDim.x * 32) {
        int nv = min(4, n - base);
        if (nv == 4) {
            const float4* srcx = reinterpret_cast<const float4*>(&g_x[(size_t)base * 64]);
            float4* srcs = reinterpret_cast<float4*>(&g_S[(size_t)base * 64]);
            float4 s0 = srcs[lane], s1 = srcs[lane + 32];
            reinterpret_cast<float4*>(sxw)[lane] = srcx[lane];
            reinterpret_cast<float4*>(sxw)[lane + 32] = srcx[lane + 32];
            reinterpret_cast<float4*>(sbw)[lane] = s0;
            reinterpret_cast<float4*>(sbw)[lane + 32] = s1;
            srcs[lane] = z4;          // rezero for next layer / next replay
            srcs[lane + 32] = z4;
        } else {
            for (int i = lane; i < 256; i += 32) {
                bool in = (i < nv * 64);
                sxw[i] = in ? g_x[(size_t)base * 64 + i] : 0.f;
                sbw[i] = in ? g_S[(size_t)base * 64 + i] : 0.f;
                if (in) g_S[(size_t)base * 64 + i] = 0.f;
            }
        }
        __syncwarp();

        float sf[4], inv[4];
#pragma unroll
        for (int j = 0; j < 4; j++) {
            sf[j] = (j < nv) ? g_sumfw[base + j] : 1.f;
            inv[j] = 1.f / fmaxf(sf[j], 1e-6f);
        }
        __syncwarp();
        if (lane < nv) g_sumfw[base + lane] = 0.f;

        // Phase 1: g = S @ Wc
        float g0[4], g1[4];
#pragma unroll
        for (int j = 0; j < 4; j++) { g0[j] = 0.f; g1[j] = 0.f; }
#pragma unroll 8
        for (int k = 0; k < 64; k += 2) {
            float2 w0 = *reinterpret_cast<const float2*>(&sWc[k * 64 + 2 * lane]);
            float2 w1 = *reinterpret_cast<const float2*>(&sWc[(k + 1) * 64 + 2 * lane]);
#pragma unroll
            for (int j = 0; j < 4; j++) {
                float2 v = *reinterpret_cast<const float2*>(&sbw[j * 64 + k]);
                g0[j] += v.x * w0.x + v.y * w1.x;
                g1[j] += v.x * w0.y + v.y * w1.y;
            }
        }

        // Phase 2: h = relu(x@U1a + b1 + inv*g + (sf*inv)*bvec)
        float h0[4], h1[4];
#pragma unroll
        for (int j = 0; j < 4; j++) {
            float r = sf[j] * inv[j];
            h0[j] = b1a + inv[j] * g0[j] + r * bv0;
            h1[j] = b1b + inv[j] * g1[j] + r * bv1;
        }
#pragma unroll 8
        for (int k = 0; k < 64; k += 2) {
            float2 w0 = *reinterpret_cast<const float2*>(&sU1[k * 64 + 2 * lane]);
            float2 w1 = *reinterpret_cast<const float2*>(&sU1[(k + 1) * 64 + 2 * lane]);
#pragma unroll
            for (int j = 0; j < 4; j++) {
                float2 v = *reinterpret_cast<const float2*>(&sxw[j * 64 + k]);
                h0[j] += v.x * w0.x + v.y * w1.x;
                h1[j] += v.x * w0.y + v.y * w1.y;
            }
        }
#pragma unroll
        for (int j = 0; j < 4; j++) {
            h0[j] = fmaxf(h0[j], 0.f);
            h1[j] = fmaxf(h1[j], 0.f);
        }
        __syncwarp();
#pragma unroll
        for (int j = 0; j < 4; j++) {
            float2 t; t.x = h0[j]; t.y = h1[j];
            *reinterpret_cast<float2*>(&sbw[j * 64 + 2 * lane]) = t;
        }
        __syncwarp();

        // Phase 3: o = relu(h@U2 + b2 + x)
        float o0[4], o1[4];
#pragma unroll
        for (int j = 0; j < 4; j++) { o0[j] = b2a; o1[j] = b2b; }
#pragma unroll 8
        for (int k = 0; k < 64; k += 2) {
            float2 w0 = *reinterpret_cast<const float2*>(&sU2[k * 64 + 2 * lane]);
            float2 w1 = *reinterpret_cast<const float2*>(&sU2[(k + 1) * 64 + 2 * lane]);
#pragma unroll
            for (int j = 0; j < 4; j++) {
                float2 v = *reinterpret_cast<const float2*>(&sbw[j * 64 + k]);
                o0[j] += v.x * w0.x + v.y * w1.x;
                o1[j] += v.x * w0.y + v.y * w1.y;
            }
        }
#pragma unroll
        for (int j = 0; j < 4; j++) {
            if (j < nv) {
                float2 xr = *reinterpret_cast<const float2*>(&sxw[j * 64 + 2 * lane]);
                float v0 = fmaxf(o0[j] + xr.x, 0.f);
                float v1 = fmaxf(o1[j] + xr.y, 0.f);
                float2 t; t.x = v0; t.y = v1;
                *reinterpret_cast<float2*>(&g_x[(size_t)(base + j) * 64 + 2 * lane]) = t;
                *reinterpret_cast<__half2*>(&g_xh[(size_t)(base + j) * 64 + 2 * lane]) =
                    __floats2half2_rn(v0, v1);
                m0 = fmaxf(m0, v0);
                m1 = fmaxf(m1, v1);
            }
        }
        __syncwarp();
    }
    if (do_max) {  // post-relu x >= 0, so uint compare == float compare
        atomicMax(reinterpret_cast<unsigned*>(&g_mx[2 * lane]), __float_as_uint(m0));
        atomicMax(reinterpret_cast<unsigned*>(&g_mx[2 * lane + 1]), __float_as_uint(m1));
    }
}

// ---------------- head: out = max_x @ head_W + head_b -----------------------
__global__ void k_head(const float* __restrict__ hW, const float* __restrict__ hb,
                       float* __restrict__ out) {
    int t = threadIdx.x;
    float v = g_mx[t] * hW[t];
#pragma unroll
    for (int o = 16; o > 0; o >>= 1) v += __shfl_xor_sync(0xffffffffu, v, o);
    __shared__ float s[2];
    if ((t & 31) == 0) s[t >> 5] = v;
    __syncthreads();
    if (t == 0) out[0] = s[0] + s[1] + hb[0];
}

// ---------------- launch ----------------------------------------------------
extern "C" void kernel_launch(void* const* d_in, const int* in_sizes, int n_in,
                              void* d_out, int out_size) {
    const float* nf = (const float*)d_in[0];
    const int* ei = (const int*)d_in[1];
    const float* ew = (const float*)d_in[2];
    const float* embW = (const float*)d_in[3];
    const float* embB = (const float*)d_in[4];
    const float* msgW1 = (const float*)d_in[5];
    const float* msgB1 = (const float*)d_in[6];
    const float* msgW2 = (const float*)d_in[7];
    const float* msgB2 = (const float*)d_in[8];
    const float* attW1 = (const float*)d_in[9];
    const float* attB1 = (const float*)d_in[10];
    const float* attW2 = (const float*)d_in[11];
    const float* attB2 = (const float*)d_in[12];
    const float* updW1 = (const float*)d_in[13];
    const float* updB1 = (const float*)d_in[14];
    const float* updW2 = (const float*)d_in[15];
    const float* updB2 = (const float*)d_in[16];
    const float* headW = (const float*)d_in[17];
    const float* headB = (const float*)d_in[18];
    float* out = (float*)d_out;

    int n = in_sizes[0] / NF;
    int ne = in_sizes[2];
    const int* row = ei;
    const int* col = ei + ne;

    cudaFuncSetAttribute(k_pre_mma, cudaFuncAttributeMaxDynamicSharedMemorySize, 41728);
    cudaFuncSetAttribute(k_update, cudaFuncAttributeMaxDynamicSharedMemorySize, 65792);

    k_wprep<<<2, 256>>>(msgW1, attW1, msgB1, attB1);
    k_fuse<<<dim3(2, 8), 256>>>(msgW2, msgB2, updW1);
    k_embed<<<1184, 256>>>(nf, embW, embB, n);
    for (int l = 0; l < 2; l++) {
        k_pre_mma<<<296, 256, 41728>>>(l, n);
        k_edge<<<2368, 128>>>(row, col, ew, attW2 + l * 32, attB2 + l, ne);
        k_update<<<444, 256, 65792>>>(l, updW1 + l * 128 * 64, updB1 + l * 64,
                                      updW2 + l * 64 * 64, updB2 + l * 64, n,
                                      (l == 1) ? 1 : 0);
    }
    k_head<<<1, 64>>>(headW, headB, out);
}

// round 12
// speedup vs baseline: 3.7827x; 1.1711x over previous
#include <cuda_runtime.h>
#include <cuda_bf16.h>
#include <cuda_fp16.h>
#include <cstdint>

#define NMAX 100000
#define NF 18

// helper: reinterpret u32 bits as __half2
__device__ __forceinline__ __half2 u32_as_half2(unsigned u) {
    __half2 h;
    *reinterpret_cast<unsigned*>(&h) = u;
    return h;
}

__device__ __forceinline__ void ldsm_x4(uint32_t& r0, uint32_t& r1, uint32_t& r2,
                                        uint32_t& r3, uint32_t addr) {
    asm volatile("ldmatrix.sync.aligned.m8n8.x4.shared.b16 {%0,%1,%2,%3}, [%4];"
                 : "=r"(r0), "=r"(r1), "=r"(r2), "=r"(r3)
                 : "r"(addr));
}
__device__ __forceinline__ void ldsm_x2(uint32_t& r0, uint32_t& r1, uint32_t addr) {
    asm volatile("ldmatrix.sync.aligned.m8n8.x2.shared.b16 {%0,%1}, [%2];"
                 : "=r"(r0), "=r"(r1)
                 : "r"(addr));
}
__device__ __forceinline__ void mma16816(float& c0, float& c1, float& c2, float& c3,
                                         uint32_t a0, uint32_t a1, uint32_t a2,
                                         uint32_t a3, uint32_t b0, uint32_t b1) {
    asm volatile(
        "mma.sync.aligned.m16n8k16.row.col.f32.f16.f16.f32 "
        "{%0,%1,%2,%3}, {%4,%5,%6,%7}, {%8,%9}, {%0,%1,%2,%3};"
        : "+f"(c0), "+f"(c1), "+f"(c2), "+f"(c3)
        : "r"(a0), "r"(a1), "r"(a2), "r"(a3), "r"(b0), "r"(b1));
}

// ---------------- scratch (device globals; no allocations allowed) ----------
__device__ __align__(128) float g_x[NMAX * 64];
__device__ __align__(128) __half g_xh[NMAX * 64];   // fp16 shadow of x
__device__ __align__(256) __half g_PR[NMAX * 128];  // [msg 64 | att 32 | pad 32]
__device__ __align__(256) __half g_PC[NMAX * 128];  // [msg 64 | att 32 | pad 32]
__device__ __align__(128) float g_S[NMAX * 64];     // segment_sum(fw * h1)
__device__ __align__(128) float g_sumfw[NMAX];
__device__ __align__(128) float g_mx[64];
__device__ __align__(128) float g_Wc[2 * 4096];     // msgW2 @ updW1b per layer (fp32 [k][n])
__device__ __align__(128) float g_bvec[2 * 64];     // msgb2 @ updW1b per layer
__device__ __align__(128) __half g_Wb[2 * 192 * 64];// fused pre-weights, [n][k] fp16
__device__ __align__(128) float g_bias[2 * 192];    // fused pre-bias (0 for PC)
__device__ __align__(128) __half g_Wu[2 * 3 * 4096];// update weights [n][k] fp16: Wc|U1a|U2

// ---------------- k_wprep: build fused fp16 pre-weight [n][k] + bias --------
__global__ __launch_bounds__(256) void k_wprep(const float* __restrict__ mW1,
                                               const float* __restrict__ aW1,
                                               const float* __restrict__ mb1,
                                               const float* __restrict__ ab1) {
    int l = blockIdx.x;
    int tid = threadIdx.x;
    const float* mW = mW1 + l * 8192;
    const float* aW = aW1 + l * 4096;
    for (int idx = tid; idx < 192 * 64; idx += 256) {
        int nn = idx >> 6, k = idx & 63;
        float v;
        if (nn < 64) v = mW[k * 64 + nn];
        else if (nn < 128) v = mW[(64 + k) * 64 + (nn - 64)];
        else if (nn < 160) v = aW[k * 32 + (nn - 128)];
        else v = aW[(64 + k) * 32 + (nn - 160)];
        g_Wb[l * 12288 + idx] = __float2half_rn(v);
    }
    for (int nn = tid; nn < 192; nn += 256) {
        float b = 0.f;
        if (nn < 64) b = mb1[l * 64 + nn];
        else if (nn >= 128 && nn < 160) b = ab1[l * 32 + (nn - 128)];
        g_bias[l * 192 + nn] = b;
    }
}

// ---------------- k_fuse: Wc = msgW2 @ updW1[64:128], bvec = msgb2 @ updW1b -
__global__ __launch_bounds__(256) void k_fuse(const float* __restrict__ msgW2,
                                              const float* __restrict__ msgB2,
                                              const float* __restrict__ updW1) {
    int l = blockIdx.x, chunk = blockIdx.y;
    __shared__ float sU1b[4096];
    const float* U1b = updW1 + l * 8192 + 4096;
    int tid = threadIdx.x;
    for (int i = tid; i < 4096; i += 256) sU1b[i] = U1b[i];
    __syncthreads();
    const float* W2 = msgW2 + l * 4096;
    int i0 = chunk * 8 + (tid >> 5);
    int o = tid & 31;
    float acc0 = 0.f, acc1 = 0.f;
#pragma unroll 8
    for (int j = 0; j < 64; j++) {
        float w = __ldg(&W2[i0 * 64 + j]);
        acc0 += w * sU1b[j * 64 + o];
        acc1 += w * sU1b[j * 64 + o + 32];
    }
    g_Wc[l * 4096 + i0 * 64 + o] = acc0;
    g_Wc[l * 4096 + i0 * 64 + o + 32] = acc1;
    if (chunk == 0 && tid < 64) {
        float acc = 0.f;
        const float* b2 = msgB2 + l * 64;
#pragma unroll 8
        for (int j = 0; j < 64; j++) acc += __ldg(&b2[j]) * sU1b[j * 64 + tid];
        g_bvec[l * 64 + tid] = acc;
    }
}

// ---------------- k_wprep2: update weights -> fp16 [n][k] (Wc | U1a | U2) ---
__global__ __launch_bounds__(256) void k_wprep2(const float* __restrict__ updW1,
                                                const float* __restrict__ updW2) {
    int l = blockIdx.x;
    int tid = threadIdx.x;
    for (int idx = tid; idx < 3 * 4096; idx += 256) {
        int part = idx >> 12;
        int rem = idx & 4095;
        int nn = rem >> 6, k = rem & 63;
        float v;
        if (part == 0) v = g_Wc[l * 4096 + k * 64 + nn];
        else if (part == 1) v = updW1[l * 8192 + k * 64 + nn];
        else v = updW2[l * 4096 + k * 64 + nn];
        g_Wu[l * 12288 + idx] = __float2half_rn(v);
    }
}

// ---------------- embed: x = relu(nf @ W + b) + zero S/sumfw/mx -------------
__global__ __launch_bounds__(256) void k_embed(const float* __restrict__ nf,
                                               const float* __restrict__ W,
                                               const float* __restrict__ b, int n) {
    __shared__ float sW[NF * 64];
    __shared__ float sb[64];
    int tid = threadIdx.x;
    for (int i = tid; i < NF * 64; i += blockDim.x) sW[i] = W[i];
    if (tid < 64) sb[tid] = b[tid];
    __syncthreads();
    int gtid = blockIdx.x * blockDim.x + tid;
    int gstr = gridDim.x * blockDim.x;
    float4 z4 = make_float4(0.f, 0.f, 0.f, 0.f);
    int q = n * 16;
    for (int i = gtid; i < q; i += gstr) reinterpret_cast<float4*>(g_S)[i] = z4;
    for (int i = gtid; i < n; i += gstr) g_sumfw[i] = 0.f;
    if (gtid < 64) g_mx[gtid] = 0.f;

    int warp = tid >> 5, lane = tid & 31;
    for (int node = blockIdx.x * 8 + warp; node < n; node += gridDim.x * 8) {
        float v = (lane < NF) ? nf[(long)node * NF + lane] : 0.f;
        float a0 = sb[2 * lane], a1 = sb[2 * lane + 1];
#pragma unroll
        for (int k = 0; k < NF; k++) {
            float xv = __shfl_sync(0xffffffffu, v, k);
            a0 += xv * sW[k * 64 + 2 * lane];
            a1 += xv * sW[k * 64 + 2 * lane + 1];
        }
        float2 r;
        r.x = fmaxf(a0, 0.f);
        r.y = fmaxf(a1, 0.f);
        *reinterpret_cast<float2*>(&g_x[(size_t)node * 64 + 2 * lane]) = r;
        *reinterpret_cast<__half2*>(&g_xh[(size_t)node * 64 + 2 * lane]) =
            __floats2half2_rn(r.x, r.y);
    }
}

// ---------------- k_pre_mma: PR/PC via tensor cores -------------------------
__global__ __launch_bounds__(256) void k_pre_mma(int l, int n) {
    extern __shared__ __align__(16) unsigned char smraw[];
    __half* sWb = reinterpret_cast<__half*>(smraw);                 // 192*64 halfs
    __half* sx = reinterpret_cast<__half*>(smraw + 24576);          // 128*64 halfs
    float* sbias = reinterpret_cast<float*>(smraw + 24576 + 16384); // 192 floats
    int tid = threadIdx.x;
    const uint4* gW = reinterpret_cast<const uint4*>(g_Wb + l * 12288);
    uint4* sW4 = reinterpret_cast<uint4*>(sWb);
    for (int i = tid; i < 1536; i += 256) {
        int r = i >> 3, c = i & 7;
        sW4[r * 8 + (c ^ (r & 7))] = gW[i];
    }
    for (int i = tid; i < 192; i += 256) sbias[i] = g_bias[l * 192 + i];
    uint32_t sx_u = (uint32_t)__cvta_generic_to_shared(sx);
    uint32_t sW_u = (uint32_t)__cvta_generic_to_shared(sWb);
    int warp = tid >> 5, lane = tid & 31;
    int nb = (n + 127) >> 7;

    for (int batch = blockIdx.x; batch < nb; batch += gridDim.x) {
        int base = batch << 7;
        __syncthreads();
        const uint4* gx = reinterpret_cast<const uint4*>(g_xh + (size_t)base * 64);
        uint4* sx4 = reinterpret_cast<uint4*>(sx);
        for (int i = tid; i < 1024; i += 256) {
            int r = i >> 3, c = i & 7;
            uint4 v = make_uint4(0, 0, 0, 0);
            if (base + r < n) v = gx[i];
            sx4[r * 8 + (c ^ (r & 7))] = v;
        }
        __syncthreads();

        uint32_t a[4][4];
        int m0 = warp * 16;
        {
            int grp = lane >> 3, lr = lane & 7;
            int r = m0 + ((grp & 1) << 3) + lr;
            int chalf = grp >> 1;
#pragma unroll
            for (int kb = 0; kb < 4; kb++) {
                int c = kb * 2 + chalf;
                uint32_t addr = sx_u + (uint32_t)((r * 8 + (c ^ (r & 7))) * 16);
                ldsm_x4(a[kb][0], a[kb][1], a[kb][2], a[kb][3], addr);
            }
        }
        int grp2 = (lane >> 3) & 1, lr2 = lane & 7;
        int mlo = base + m0 + (lane >> 2);
        int mhi = mlo + 8;
#pragma unroll 1
        for (int t = 0; t < 24; t++) {
            float c0 = 0.f, c1 = 0.f, c2 = 0.f, c3 = 0.f;
#pragma unroll
            for (int kb = 0; kb < 4; kb++) {
                int nrow = t * 8 + lr2;
                int cch = kb * 2 + grp2;
                uint32_t baddr =
                    sW_u + (uint32_t)((nrow * 8 + (cch ^ (nrow & 7))) * 16);
                uint32_t b0, b1;
                ldsm_x2(b0, b1, baddr);
                mma16816(c0, c1, c2, c3, a[kb][0], a[kb][1], a[kb][2], a[kb][3],
                         b0, b1);
            }
            int nloc = t * 8 + 2 * (lane & 3);
            float bsa = sbias[nloc], bsb = sbias[nloc + 1];
            c0 += bsa; c1 += bsb; c2 += bsa; c3 += bsb;
            __half* dst;
            int off;
            if (t < 8) { dst = g_PR; off = nloc; }
            else if (t < 16) { dst = g_PC; off = nloc - 64; }
            else if (t < 20) { dst = g_PR; off = nloc - 64; }
            else { dst = g_PC; off = nloc - 96; }
            if (mlo < n)
                *reinterpret_cast<__half2*>(dst + (size_t)mlo * 128 + off) =
                    __floats2half2_rn(c0, c1);
            if (mhi < n)
                *reinterpret_cast<__half2*>(dst + (size_t)mhi * 128 + off) =
                    __floats2half2_rn(c2, c3);
        }
    }
}

// ---------------- edge kernel: half-warp per edge, padded aligned rows ------
__global__ __launch_bounds__(128) void k_edge(const int* __restrict__ row,
                                              const int* __restrict__ col,
                                              const float* __restrict__ ew,
                                              const float* __restrict__ aW2,
                                              const float* __restrict__ ab2, int ne) {
    __shared__ float s_aw2[32];
    if (threadIdx.x < 32) s_aw2[threadIdx.x] = aW2[threadIdx.x];
    __syncthreads();
    int warpsPerBlk = blockDim.x >> 5;
    int W = gridDim.x * warpsPerBlk;
    int w = blockIdx.x * warpsPerBlk + (threadIdx.x >> 5);
    int hl = threadIdx.x & 15;
    int half = (threadIdx.x >> 4) & 1;
    float2 aw;
    aw.x = s_aw2[2 * hl];
    aw.y = s_aw2[2 * hl + 1];
    float ab2v = __ldg(ab2);
    int S = 2 * W;
    const __half2 z2 = __float2half2_rn(0.f);

    for (int eb = 2 * w; eb < ne; eb += 2 * S) {
        int e0 = eb + half;
        int e1 = e0 + S;
        bool v0 = e0 < ne;
        bool v1 = e1 < ne;
        int e0c = v0 ? e0 : 0;
        int e1c = v1 ? e1 : 0;
        int r0 = row[e0c], c0 = col[e0c];
        int r1 = row[e1c], c1 = col[e1c];
        float w0 = ew[e0c], w1 = ew[e1c];

        const __half* pr0 = g_PR + (size_t)r0 * 128;
        const __half* pc0 = g_PC + (size_t)c0 * 128;
        const __half* pr1 = g_PR + (size_t)r1 * 128;
        const __half* pc1 = g_PC + (size_t)c1 * 128;

        uint2 pm0r = __ldg(reinterpret_cast<const uint2*>(pr0 + 4 * hl));
        uint2 pm0c = __ldg(reinterpret_cast<const uint2*>(pc0 + 4 * hl));
        uint2 pm1r = __ldg(reinterpret_cast<const uint2*>(pr1 + 4 * hl));
        uint2 pm1c = __ldg(reinterpret_cast<const uint2*>(pc1 + 4 * hl));
        __half2 pa0r = __ldg(reinterpret_cast<const __half2*>(pr0 + 64 + 2 * hl));
        __half2 pa0c = __ldg(reinterpret_cast<const __half2*>(pc0 + 64 + 2 * hl));
        __half2 pa1r = __ldg(reinterpret_cast<const __half2*>(pr1 + 64 + 2 * hl));
        __half2 pa1c = __ldg(reinterpret_cast<const __half2*>(pc1 + 64 + 2 * hl));

        float2 a0f = __half22float2(__hmax2(__hadd2(pa0r, pa0c), z2));
        float2 a1f = __half22float2(__hmax2(__hadd2(pa1r, pa1c), z2));
        float t0 = a0f.x * aw.x + a0f.y * aw.y;
        float t1 = a1f.x * aw.x + a1f.y * aw.y;
#pragma unroll
        for (int o = 8; o > 0; o >>= 1) {
            t0 += __shfl_xor_sync(0xffffffffu, t0, o);
            t1 += __shfl_xor_sync(0xffffffffu, t1, o);
        }
        float fw0 = w0 / (1.f + __expf(-(t0 + ab2v)));
        float fw1 = w1 / (1.f + __expf(-(t1 + ab2v)));

        float2 f00 = __half22float2(__hmax2(__hadd2(u32_as_half2(pm0r.x), u32_as_half2(pm0c.x)), z2));
        float2 f01 = __half22float2(__hmax2(__hadd2(u32_as_half2(pm0r.y), u32_as_half2(pm0c.y)), z2));
        float2 f10 = __half22float2(__hmax2(__hadd2(u32_as_half2(pm1r.x), u32_as_half2(pm1c.x)), z2));
        float2 f11 = __half22float2(__hmax2(__hadd2(u32_as_half2(pm1r.y), u32_as_half2(pm1c.y)), z2));

        if (v0) {
            float* d0 = &g_S[(size_t)c0 * 64 + 4 * hl];
            asm volatile("red.global.add.v4.f32 [%0], {%1,%2,%3,%4};" ::"l"(d0),
                         "f"(f00.x * fw0), "f"(f00.y * fw0), "f"(f01.x * fw0),
                         "f"(f01.y * fw0)
                         : "memory");
            if (hl == 0) atomicAdd(&g_sumfw[c0], fw0);
        }
        if (v1) {
            float* d1 = &g_S[(size_t)c1 * 64 + 4 * hl];
            asm volatile("red.global.add.v4.f32 [%0], {%1,%2,%3,%4};" ::"l"(d1),
                         "f"(f10.x * fw1), "f"(f10.y * fw1), "f"(f11.x * fw1),
                         "f"(f11.y * fw1)
                         : "memory");
            if (hl == 0) atomicAdd(&g_sumfw[c1], fw1);
        }
    }
}

// ---------------- k_update_mma: tensor-core fused update --------------------
// h = relu(b1 + inv*(S@Wc) + (sf*inv)*bvec + X@U1a); o = relu(h@U2 + b2 + x)
__global__ __launch_bounds__(256) void k_update_mma(int l,
                                                    const float* __restrict__ ub1,
                                                    const float* __restrict__ ub2,
                                                    int n, int do_max) {
    extern __shared__ __align__(16) unsigned char smraw[];
    __half* sW = reinterpret_cast<__half*>(smraw);          // 3*4096 halfs (24576B)
    __half* sx = reinterpret_cast<__half*>(smraw + 24576);  // 8192 halfs (16384B)
    __half* sh = reinterpret_cast<__half*>(smraw + 40960);  // S then H (16384B)
    float* sb = reinterpret_cast<float*>(smraw + 57344);    // 192: b1|b2|bvec
    float* ssf = sb + 192;                                  // 128
    unsigned* smx = reinterpret_cast<unsigned*>(ssf + 128); // 64
    int tid = threadIdx.x;

    // stage weights (swizzled), biases
    {
        const uint4* gW = reinterpret_cast<const uint4*>(g_Wu + l * 12288);
        uint4* sW4 = reinterpret_cast<uint4*>(sW);
        for (int i = tid; i < 1536; i += 256) {
            int r = i >> 3, c = i & 7;
            sW4[r * 8 + (c ^ (r & 7))] = gW[i];
        }
        if (tid < 64) {
            sb[tid] = ub1[tid];
            sb[64 + tid] = ub2[tid];
            sb[128 + tid] = g_bvec[l * 64 + tid];
            smx[tid] = 0u;
        }
    }
    uint32_t sx_u = (uint32_t)__cvta_generic_to_shared(sx);
    uint32_t sh_u = (uint32_t)__cvta_generic_to_shared(sh);
    uint32_t sW_u = (uint32_t)__cvta_generic_to_shared(sW);
    int warp = tid >> 5, lane = tid & 31;
    int m0 = warp * 16;
    int grp = lane >> 3, lr = lane & 7;
    int afr = m0 + ((grp & 1) << 3) + lr;
    int achalf = grp >> 1;
    int grp2 = (lane >> 3) & 1, lr2 = lane & 7;
    int rlo = m0 + (lane >> 2), rhi = rlo + 8;
    int nb = (n + 127) >> 7;
    float mxa[8], mxb[8];
#pragma unroll
    for (int t = 0; t < 8; t++) { mxa[t] = 0.f; mxb[t] = 0.f; }
    float4 z4 = make_float4(0.f, 0.f, 0.f, 0.f);

    for (int batch = blockIdx.x; batch < nb; batch += gridDim.x) {
        int base = batch << 7;
        __syncthreads();
        // stage X (fp16) and S (fp32->fp16, fused rezero)
        {
            const uint4* gx = reinterpret_cast<const uint4*>(g_xh + (size_t)base * 64);
            uint4* sx4 = reinterpret_cast<uint4*>(sx);
            uint4* sh4 = reinterpret_cast<uint4*>(sh);
            float4* gs4 = reinterpret_cast<float4*>(g_S + (size_t)base * 64);
            for (int i = tid; i < 1024; i += 256) {
                int r = i >> 3, c = i & 7;
                uint4 vx = make_uint4(0, 0, 0, 0);
                uint4 vs = make_uint4(0, 0, 0, 0);
                if (base + r < n) {
                    vx = gx[i];
                    float4 f0 = gs4[2 * i];
                    float4 f1 = gs4[2 * i + 1];
                    gs4[2 * i] = z4;
                    gs4[2 * i + 1] = z4;
                    __half2 h0 = __floats2half2_rn(f0.x, f0.y);
                    __half2 h1 = __floats2half2_rn(f0.z, f0.w);
                    __half2 h2 = __floats2half2_rn(f1.x, f1.y);
                    __half2 h3 = __floats2half2_rn(f1.z, f1.w);
                    vs.x = *reinterpret_cast<unsigned*>(&h0);
                    vs.y = *reinterpret_cast<unsigned*>(&h1);
                    vs.z = *reinterpret_cast<unsigned*>(&h2);
                    vs.w = *reinterpret_cast<unsigned*>(&h3);
                }
                int d = (i >> 3) * 8 + ((i & 7) ^ ((i >> 3) & 7));
                sx4[d] = vx;
                sh4[d] = vs;
            }
            if (tid < 128) {
                float sf = 1.f;
                if (base + tid < n) {
                    sf = g_sumfw[base + tid];
                    g_sumfw[base + tid] = 0.f;
                }
                ssf[tid] = sf;
            }
        }
        __syncthreads();

        // load A fragments: S (from sh) and X (from sx)
        uint32_t aS[4][4], aX[4][4];
#pragma unroll
        for (int kb = 0; kb < 4; kb++) {
            int c = kb * 2 + achalf;
            uint32_t off = (uint32_t)((afr * 8 + (c ^ (afr & 7))) * 16);
            ldsm_x4(aS[kb][0], aS[kb][1], aS[kb][2], aS[kb][3], sh_u + off);
            ldsm_x4(aX[kb][0], aX[kb][1], aX[kb][2], aX[kb][3], sx_u + off);
        }
        float sflo = ssf[rlo], sfhi = ssf[rhi];
        float invlo = 1.f / fmaxf(sflo, 1e-6f);
        float invhi = 1.f / fmaxf(sfhi, 1e-6f);
        float ratlo = sflo * invlo, rathi = sfhi * invhi;

        // phase 1+2 per n-tile: G = S@Wc, Hx = X@U1a, combine, store h to sh
#pragma unroll 1
        for (int t = 0; t < 8; t++) {
            float g0 = 0.f, g1 = 0.f, g2 = 0.f, g3 = 0.f;
            float h0 = 0.f, h1 = 0.f, h2 = 0.f, h3 = 0.f;
            int nrow = t * 8 + lr2;
#pragma unroll
            for (int kb = 0; kb < 4; kb++) {
                int cch = kb * 2 + grp2;
                uint32_t off = (uint32_t)((nrow * 8 + (cch ^ (nrow & 7))) * 16);
                uint32_t b0, b1;
                ldsm_x2(b0, b1, sW_u + off);
                mma16816(g0, g1, g2, g3, aS[kb][0], aS[kb][1], aS[kb][2], aS[kb][3], b0, b1);
                ldsm_x2(b0, b1, sW_u + 8192u + off);
                mma16816(h0, h1, h2, h3, aX[kb][0], aX[kb][1], aX[kb][2], aX[kb][3], b0, b1);
            }
            int nloc = t * 8 + 2 * (lane & 3);
            float b1a = sb[nloc], b1b = sb[nloc + 1];
            float bva = sb[128 + nloc], bvb = sb[128 + nloc + 1];
            float v0 = fmaxf(b1a + invlo * g0 + ratlo * bva + h0, 0.f);
            float v1 = fmaxf(b1b + invlo * g1 + ratlo * bvb + h1, 0.f);
            float v2 = fmaxf(b1a + invhi * g2 + rathi * bva + h2, 0.f);
            float v3 = fmaxf(b1b + invhi * g3 + rathi * bvb + h3, 0.f);
            // store h into sh (overwrites consumed S tile; own rows only)
            *reinterpret_cast<__half2*>(
                sh + (size_t)((rlo * 8 + (t ^ (rlo & 7))) * 8 + 2 * (lane & 3))) =
                __floats2half2_rn(v0, v1);
            *reinterpret_cast<__half2*>(
                sh + (size_t)((rhi * 8 + (t ^ (rhi & 7))) * 8 + 2 * (lane & 3))) =
                __floats2half2_rn(v2, v3);
        }
        __syncwarp();

        // reload H fragments
#pragma unroll
        for (int kb = 0; kb < 4; kb++) {
            int c = kb * 2 + achalf;
            uint32_t off = (uint32_t)((afr * 8 + (c ^ (afr & 7))) * 16);
            ldsm_x4(aS[kb][0], aS[kb][1], aS[kb][2], aS[kb][3], sh_u + off);
        }

        // phase 3: O = H@U2 + b2 + x; relu; store; max
        bool vlo = (base + rlo) < n, vhi = (base + rhi) < n;
#pragma unroll 1
        for (int t = 0; t < 8; t++) {
            float o0 = 0.f, o1 = 0.f, o2 = 0.f, o3 = 0.f;
            int nrow = t * 8 + lr2;
#pragma unroll
            for (int kb = 0; kb < 4; kb++) {
                int cch = kb * 2 + grp2;
                uint32_t off = (uint32_t)((nrow * 8 + (cch ^ (nrow & 7))) * 16);
                uint32_t b0, b1;
                ldsm_x2(b0, b1, sW_u + 16384u + off);
                mma16816(o0, o1, o2, o3, aS[kb][0], aS[kb][1], aS[kb][2], aS[kb][3], b0, b1);
            }
            int nloc = t * 8 + 2 * (lane & 3);
            float b2a = sb[64 + nloc], b2b = sb[64 + nloc + 1];
            float2 xlo = __half22float2(*reinterpret_cast<const __half2*>(
                sx + (size_t)((rlo * 8 + (t ^ (rlo & 7))) * 8 + 2 * (lane & 3))));
            float2 xhi = __half22float2(*reinterpret_cast<const __half2*>(
                sx + (size_t)((rhi * 8 + (t ^ (rhi & 7))) * 8 + 2 * (lane & 3))));
            float r0 = fmaxf(o0 + b2a + xlo.x, 0.f);
            float r1 = fmaxf(o1 + b2b + xlo.y, 0.f);
            float r2 = fmaxf(o2 + b2a + xhi.x, 0.f);
            float r3 = fmaxf(o3 + b2b + xhi.y, 0.f);
            if (vlo) {
                float2 t2; t2.x = r0; t2.y = r1;
                *reinterpret_cast<float2*>(&g_x[(size_t)(base + rlo) * 64 + nloc]) = t2;
                *reinterpret_cast<__half2*>(&g_xh[(size_t)(base + rlo) * 64 + nloc]) =
                    __floats2half2_rn(r0, r1);
                mxa[t] = fmaxf(mxa[t], r0);
                mxb[t] = fmaxf(mxb[t], r1);
            }
            if (vhi) {
                float2 t2; t2.x = r2; t2.y = r3;
                *reinterpret_cast<float2*>(&g_x[(size_t)(base + rhi) * 64 + nloc]) = t2;
                *reinterpret_cast<__half2*>(&g_xh[(size_t)(base + rhi) * 64 + nloc]) =
                    __floats2half2_rn(r2, r3);
                mxa[t] = fmaxf(mxa[t], r2);
                mxb[t] = fmaxf(mxb[t], r3);
            }
        }
    }

    if (do_max) {
        __syncthreads();
#pragma unroll
        for (int t = 0; t < 8; t++) {
            int nloc = t * 8 + 2 * (lane & 3);
            atomicMax(&smx[nloc], __float_as_uint(mxa[t]));
            atomicMax(&smx[nloc + 1], __float_as_uint(mxb[t]));
        }
        __syncthreads();
        if (tid < 64)
            atomicMax(reinterpret_cast<unsigned*>(&g_mx[tid]), smx[tid]);
    }
}

// ---------------- head: out = max_x @ head_W + head_b -----------------------
__global__ void k_head(const float* __restrict__ hW, const float* __restrict__ hb,
                       float* __restrict__ out) {
    int t = threadIdx.x;
    float v = g_mx[t] * hW[t];
#pragma unroll
    for (int o = 16; o > 0; o >>= 1) v += __shfl_xor_sync(0xffffffffu, v, o);
    __shared__ float s[2];
    if ((t & 31) == 0) s[t >> 5] = v;
    __syncthreads();
    if (t == 0) out[0] = s[0] + s[1] + hb[0];
}

// ---------------- launch ----------------------------------------------------
extern "C" void kernel_launch(void* const* d_in, const int* in_sizes, int n_in,
                              void* d_out, int out_size) {
    const float* nf = (const float*)d_in[0];
    const int* ei = (const int*)d_in[1];
    const float* ew = (const float*)d_in[2];
    const float* embW = (const float*)d_in[3];
    const float* embB = (const float*)d_in[4];
    const float* msgW1 = (const float*)d_in[5];
    const float* msgB1 = (const float*)d_in[6];
    const float* msgW2 = (const float*)d_in[7];
    const float* msgB2 = (const float*)d_in[8];
    const float* attW1 = (const float*)d_in[9];
    const float* attB1 = (const float*)d_in[10];
    const float* attW2 = (const float*)d_in[11];
    const float* attB2 = (const float*)d_in[12];
    const float* updW1 = (const float*)d_in[13];
    const float* updB1 = (const float*)d_in[14];
    const float* updW2 = (const float*)d_in[15];
    const float* updB2 = (const float*)d_in[16];
    const float* headW = (const float*)d_in[17];
    const float* headB = (const float*)d_in[18];
    float* out = (float*)d_out;

    int n = in_sizes[0] / NF;
    int ne = in_sizes[2];
    const int* row = ei;
    const int* col = ei + ne;

    cudaFuncSetAttribute(k_pre_mma, cudaFuncAttributeMaxDynamicSharedMemorySize, 41728);
    cudaFuncSetAttribute(k_update_mma, cudaFuncAttributeMaxDynamicSharedMemorySize, 59904);

    k_wprep<<<2, 256>>>(msgW1, attW1, msgB1, attB1);
    k_fuse<<<dim3(2, 8), 256>>>(msgW2, msgB2, updW1);
    k_wprep2<<<2, 256>>>(updW1, updW2);
    k_embed<<<1184, 256>>>(nf, embW, embB, n);
    for (int l = 0; l < 2; l++) {
        k_pre_mma<<<296, 256, 41728>>>(l, n);
        k_edge<<<2368, 128>>>(row, col, ew, attW2 + l * 32, attB2 + l, ne);
        k_update_mma<<<444, 256, 59904>>>(l, updB1 + l * 64, updB2 + l * 64, n,
                                          (l == 1) ? 1 : 0);
    }
    k_head<<<1, 64>>>(headW, headB, out);
}